// round 4
// baseline (speedup 1.0000x reference)
#include <cuda_runtime.h>
#include <cuda_bf16.h>
#include <stdint.h>

#define TINV 10.0f

__device__ float d_agn[128 * 128];
__device__ float d_offac[128 * 1024];               // invnorm * maxabs / 127 per column
__device__ signed char d_ofi[128ull * 1024 * 256];  // int8, [bb][s][d]; bb: q 0-63, k 64-127
__device__ float d_xn[2][64 * 1024 * 128];          // normalized x, [b][s][c]
__device__ unsigned long long d_rowbest[64 * 1024];
__device__ unsigned long long d_colbest[64 * 1024];
__device__ double d_gsum, d_dsum;

// ---------------- helpers ----------------
__device__ __forceinline__ uint32_t smem_u32(const void* p) {
    uint32_t a;
    asm("{ .reg .u64 t; cvta.to.shared.u64 t, %1; cvt.u32.u64 %0, t; }" : "=r"(a) : "l"(p));
    return a;
}
__device__ __forceinline__ uint32_t fkey(float f) {
    uint32_t u = __float_as_uint(f);
    return (u & 0x80000000u) ? ~u : (u | 0x80000000u);
}
__device__ __forceinline__ unsigned long long packkey(float v, uint32_t idx) {
    return ((unsigned long long)fkey(v) << 32) | (unsigned long long)(0xFFFFFFFFu - idx);
}
__device__ __forceinline__ unsigned long long shflx64(unsigned long long v, int m) {
    return __shfl_xor_sync(0xFFFFFFFFu, v, m);
}
__device__ __forceinline__ void cp16(uint32_t dst, const void* src) {
    asm volatile("cp.async.cg.shared.global [%0],[%1],16;\n" :: "r"(dst), "l"(src));
}
#define CP_COMMIT() asm volatile("cp.async.commit_group;\n" ::: "memory")
__device__ __forceinline__ void ldsm4(uint32_t& r0, uint32_t& r1, uint32_t& r2,
                                      uint32_t& r3, uint32_t a) {
    asm volatile("ldmatrix.sync.aligned.m8n8.x4.shared.b16 {%0,%1,%2,%3},[%4];\n"
                 : "=r"(r0), "=r"(r1), "=r"(r2), "=r"(r3) : "r"(a));
}
__device__ __forceinline__ void mma_s8(int* c, const uint32_t* a, const uint32_t* b) {
    asm volatile("mma.sync.aligned.m16n8k32.row.col.s32.s8.s8.s32 "
                 "{%0,%1,%2,%3},{%4,%5,%6,%7},{%8,%9},{%0,%1,%2,%3};\n"
                 : "+r"(c[0]), "+r"(c[1]), "+r"(c[2]), "+r"(c[3])
                 : "r"(a[0]), "r"(a[1]), "r"(a[2]), "r"(a[3]), "r"(b[0]), "r"(b[1]));
}

// ---------------- K0: init ----------------
__global__ void k_init() {
    int i = blockIdx.x * blockDim.x + threadIdx.x;
    if (i < 64 * 1024) { d_rowbest[i] = 0ULL; d_colbest[i] = 0ULL; }
    if (i == 0) { d_gsum = 0.0; d_dsum = 0.0; }
}

// ---------------- global loss ----------------
__global__ void k_agn(const float* __restrict__ agq, const float* __restrict__ agk) {
    int row = blockIdx.x, c = threadIdx.x;
    const float* src = (row < 64) ? (agq + row * 128) : (agk + (row - 64) * 128);
    float v = src[c];
    __shared__ float red[128];
    red[c] = v * v; __syncthreads();
    for (int off = 64; off; off >>= 1) { if (c < off) red[c] += red[c + off]; __syncthreads(); }
    d_agn[row * 128 + c] = v / fmaxf(sqrtf(red[0]), 1e-12f);
}
__global__ void k_global() {
    int i = blockIdx.x, j = threadIdx.x;
    __shared__ float ai[128], red[128], s_pos;
    ai[j] = d_agn[i * 128 + j];
    __syncthreads();
    float dot = 0.0f;
#pragma unroll 8
    for (int c = 0; c < 128; c++) dot += ai[c] * d_agn[j * 128 + c];
    float lg = dot * TINV;
    if (j == ((i + 64) & 127)) s_pos = lg;
    float v = (j == i) ? -1e30f : lg;
    red[j] = v; __syncthreads();
    for (int off = 64; off; off >>= 1) { if (j < off) red[j] = fmaxf(red[j], red[j + off]); __syncthreads(); }
    float mx = red[0]; __syncthreads();
    red[j] = expf(v - mx); __syncthreads();
    for (int off = 64; off; off >>= 1) { if (j < off) red[j] += red[j + off]; __syncthreads(); }
    if (j == 0) atomicAdd(&d_gsum, (double)(logf(red[0]) + mx - s_pos));
}

// ---------------- of: transpose -> [s][d] int8 + per-column fac ----------------
__global__ void __launch_bounds__(256) k_prep_of(const float* __restrict__ ofq,
                                                 const float* __restrict__ ofk) {
    __shared__ float sh[32 * 257];
    int bb = blockIdx.y, s0 = blockIdx.x * 32, tid = threadIdx.x;
    const float* p = (bb < 64 ? ofq : ofk) + (size_t)(bb & 63) * 256 * 1024;
#pragma unroll 8
    for (int it = 0; it < 32; it++) {
        int idx = it * 256 + tid, dd = idx >> 5, s = idx & 31;
        sh[s * 257 + dd] = p[(size_t)dd * 1024 + s0 + s];
    }
    __syncthreads();
    int s = tid >> 3, part = tid & 7, d0 = part * 32;
    const float* row = &sh[s * 257 + d0];
    float v[32];
    float mx = 0.0f, ss = 0.0f;
#pragma unroll
    for (int ii = 0; ii < 16; ii++) {
        int i = (ii + part * 2) & 15;  // stagger -> conflict-free
        float a = row[2 * i], b2 = row[2 * i + 1];
        v[2 * i] = a; v[2 * i + 1] = b2;
        mx = fmaxf(mx, fmaxf(fabsf(a), fabsf(b2)));
        ss += a * a + b2 * b2;
    }
#pragma unroll
    for (int m = 1; m < 8; m <<= 1) {
        mx = fmaxf(mx, __shfl_xor_sync(0xFFFFFFFFu, mx, m));
        ss += __shfl_xor_sync(0xFFFFFFFFu, ss, m);
    }
    float scl = (mx > 0.0f) ? 127.0f / mx : 0.0f;
    if (part == 0)
        d_offac[bb * 1024 + s0 + s] = mx / (127.0f * fmaxf(sqrtf(ss), 1e-12f));
    uint32_t pk[8];
#pragma unroll
    for (int j = 0; j < 8; j++) {
        int q0 = max(-127, min(127, __float2int_rn(v[4 * j] * scl)));
        int q1 = max(-127, min(127, __float2int_rn(v[4 * j + 1] * scl)));
        int q2 = max(-127, min(127, __float2int_rn(v[4 * j + 2] * scl)));
        int q3 = max(-127, min(127, __float2int_rn(v[4 * j + 3] * scl)));
        pk[j] = (uint32_t)(q0 & 255) | ((uint32_t)(q1 & 255) << 8) |
                ((uint32_t)(q2 & 255) << 16) | ((uint32_t)q3 << 24);
    }
    uint4* dst = (uint4*)(d_ofi + ((size_t)bb * 1024 + s0 + s) * 256 + d0);
    dst[0] = make_uint4(pk[0], pk[1], pk[2], pk[3]);
    dst[1] = make_uint4(pk[4], pk[5], pk[6], pk[7]);
}

// ---------------- x: normalize over C + transpose ----------------
__global__ void k_prep_x(const float* __restrict__ xq, const float* __restrict__ xk) {
    __shared__ float sh[128 * 33];
    __shared__ float invs[32];
    int bb = blockIdx.y, s0 = blockIdx.x * 32, tid = threadIdx.x;
    const float* src = (bb < 64 ? xq : xk) + (size_t)(bb & 63) * 128 * 1024;
    float* dst = d_xn[bb < 64 ? 0 : 1] + (size_t)(bb & 63) * 1024 * 128;
#pragma unroll
    for (int it = 0; it < 16; it++) {
        int idx = it * 256 + tid, c = idx >> 5, s = idx & 31;
        sh[c * 33 + s] = src[(size_t)c * 1024 + s0 + s];
    }
    __syncthreads();
    if (tid < 32) {
        float acc = 0.0f;
#pragma unroll 8
        for (int c = 0; c < 128; c++) { float v = sh[c * 33 + tid]; acc += v * v; }
        invs[tid] = 1.0f / fmaxf(sqrtf(acc), 1e-12f);
    }
    __syncthreads();
#pragma unroll
    for (int it = 0; it < 16; it++) {
        int idx = it * 256 + tid, s = idx >> 7, c = idx & 127;
        dst[(size_t)(s0 + s) * 128 + c] = sh[c * 33 + s] * invs[s];
    }
}

// ---------------- sim GEMM (int8 IMMA) + fused dual argmax ----------------
// CTA tile 128(s) x 128(t), K=256. grid (8,8,64), 256 threads, 64KB dyn smem.
#define SIM_SMEM 65536
__global__ void __launch_bounds__(256) k_simargmax() {
    extern __shared__ __align__(16) char dsm[];
    __shared__ float qf[128], kf[128];
    __shared__ unsigned long long s_row[128], s_col[128];
    char* As = dsm;
    char* Bs = dsm + 32768;
    int tid = threadIdx.x, lane = tid & 31, wid = tid >> 5;
    int b = blockIdx.z, s0 = blockIdx.y * 128, t0 = blockIdx.x * 128;
    const signed char* Aq = d_ofi + ((size_t)b * 1024 + s0) * 256;
    const signed char* Bq = d_ofi + ((size_t)(64 + b) * 1024 + t0) * 256;

    if (tid < 128) { qf[tid] = d_offac[b * 1024 + s0 + tid]; s_row[tid] = 0ULL; }
    else { kf[tid - 128] = d_offac[(64 + b) * 1024 + t0 + tid - 128]; s_col[tid - 128] = 0ULL; }

    uint32_t a_base = smem_u32(As), b_base = smem_u32(Bs);
    // issue all loads: 4 commit groups of K-64 each (A+B)
#pragma unroll
    for (int c = 0; c < 4; c++) {
#pragma unroll
        for (int it = 0; it < 2; it++) {
            int idx = it * 256 + tid;
            int row = idx >> 2, uu = idx & 3, u = c * 4 + uu;
            uint32_t swo = (uint32_t)row * 256 + (uint32_t)((u ^ (row & 7)) << 4);
            cp16(a_base + swo, Aq + (size_t)row * 256 + u * 16);
            cp16(b_base + swo, Bq + (size_t)row * 256 + u * 16);
        }
        CP_COMMIT();
    }

    int wm = wid & 1, wn = wid >> 1;
    int row_in = lane & 15, ub = lane >> 4;
    int acc[4][4][4];
#pragma unroll
    for (int mi = 0; mi < 4; mi++)
#pragma unroll
        for (int ni = 0; ni < 4; ni++)
#pragma unroll
            for (int r = 0; r < 4; r++) acc[mi][ni][r] = 0;

#define DO_CHUNK(C, W) do { \
    asm volatile("cp.async.wait_group %0;\n" :: "n"(W) : "memory"); \
    __syncthreads(); \
    _Pragma("unroll") \
    for (int ks = 0; ks < 2; ks++) { \
        int ubase = ((C) * 2 + ks) * 2 + ub; \
        uint32_t af[4][4], bfr[4][2]; \
        _Pragma("unroll") \
        for (int mi = 0; mi < 4; mi++) { \
            int r = wm * 64 + mi * 16 + row_in; \
            ldsm4(af[mi][0], af[mi][1], af[mi][2], af[mi][3], \
                  a_base + (uint32_t)r * 256 + (uint32_t)((ubase ^ (r & 7)) << 4)); \
        } \
        _Pragma("unroll") \
        for (int np = 0; np < 2; np++) { \
            int r = wn * 32 + np * 16 + row_in; \
            uint32_t r0, r1, r2, r3; \
            ldsm4(r0, r1, r2, r3, \
                  b_base + (uint32_t)r * 256 + (uint32_t)((ubase ^ (r & 7)) << 4)); \
            bfr[np * 2][0] = r0; bfr[np * 2][1] = r2; \
            bfr[np * 2 + 1][0] = r1; bfr[np * 2 + 1][1] = r3; \
        } \
        _Pragma("unroll") \
        for (int mi = 0; mi < 4; mi++) \
            _Pragma("unroll") \
            for (int ni = 0; ni < 4; ni++) \
                mma_s8(acc[mi][ni], af[mi], bfr[ni]); \
    } } while (0)

    DO_CHUNK(0, 3);
    DO_CHUNK(1, 2);
    DO_CHUNK(2, 1);
    DO_CHUNK(3, 0);
#undef DO_CHUNK

    int g = lane >> 2, tg = lane & 3;
    // row argmax (over t): weight kf[t]
#pragma unroll
    for (int mi = 0; mi < 4; mi++)
#pragma unroll
        for (int rh = 0; rh < 2; rh++) {
            unsigned long long best = 0ULL;
#pragma unroll
            for (int ni = 0; ni < 4; ni++)
#pragma unroll
                for (int cp = 0; cp < 2; cp++) {
                    int tl = wn * 32 + ni * 8 + 2 * tg + cp;
                    float vv = (float)acc[mi][ni][rh * 2 + cp] * kf[tl];
                    unsigned long long k2 = packkey(vv, (uint32_t)(t0 + tl));
                    best = (k2 > best) ? k2 : best;
                }
            unsigned long long o;
            o = shflx64(best, 1); best = (o > best) ? o : best;
            o = shflx64(best, 2); best = (o > best) ? o : best;
            if (tg == 0)
                atomicMax(&s_row[wm * 64 + mi * 16 + g + 8 * rh], best);
        }
    // col argmax (over s): weight qf[s]
#pragma unroll
    for (int ni = 0; ni < 4; ni++)
#pragma unroll
        for (int cp = 0; cp < 2; cp++) {
            int tl = wn * 32 + ni * 8 + 2 * tg + cp;
            unsigned long long best = 0ULL;
#pragma unroll
            for (int mi = 0; mi < 4; mi++)
#pragma unroll
                for (int rh = 0; rh < 2; rh++) {
                    int sl = wm * 64 + mi * 16 + g + 8 * rh;
                    float vv = (float)acc[mi][ni][rh * 2 + cp] * qf[sl];
                    unsigned long long k2 = packkey(vv, (uint32_t)(s0 + sl));
                    best = (k2 > best) ? k2 : best;
                }
            unsigned long long o;
            o = shflx64(best, 4);  best = (o > best) ? o : best;
            o = shflx64(best, 8);  best = (o > best) ? o : best;
            o = shflx64(best, 16); best = (o > best) ? o : best;
            if (g == 0) atomicMax(&s_col[tl], best);
        }
    __syncthreads();
    if (tid < 128) atomicMax(&d_rowbest[(size_t)b * 1024 + s0 + tid], s_row[tid]);
    else atomicMax(&d_colbest[(size_t)b * 1024 + t0 + tid - 128], s_col[tid - 128]);
}

// ---------------- dense losses ----------------
__global__ void __launch_bounds__(256) k_dense(const float* __restrict__ adq,
                                               const float* __restrict__ adk) {
    int b = blockIdx.y, dir = blockIdx.z, s0 = blockIdx.x * 128;
    const float* xA = d_xn[dir] + (size_t)b * 1024 * 128;
    const float* xB = d_xn[dir ^ 1] + (size_t)b * 1024 * 128;
    const float* ad = dir ? adq : adk;
    const unsigned long long* best = dir ? d_colbest : d_rowbest;

    __shared__ __align__(16) float sbuf[128 * 64 + 128];
    float* Ls = sbuf;
    float* posv = sbuf + 128 * 64;
    float* xs = sbuf;
    float* ads = sbuf + 128 * 33;

    int tid = threadIdx.x, sgp = tid >> 3, jg = tid & 7;
    float accL[4][8];
#pragma unroll
    for (int i = 0; i < 4; i++)
#pragma unroll
        for (int k = 0; k < 8; k++) accL[i][k] = 0.0f;

    for (int cc = 0; cc < 4; cc++) {
        __syncthreads();
        int c0 = cc * 32;
#pragma unroll
        for (int it = 0; it < 16; it++) {
            int idx = it * 256 + tid, r = idx >> 5, c = idx & 31;
            xs[r * 33 + c] = xA[(size_t)(s0 + r) * 128 + c0 + c];
        }
#pragma unroll
        for (int it = 0; it < 8; it++) {
            int idx = it * 256 + tid, j = idx >> 5, c = idx & 31;
            ads[j * 33 + c] = ad[j * 128 + c0 + c];
        }
        __syncthreads();
#pragma unroll 4
        for (int c = 0; c < 32; c++) {
            float a[4], bb[8];
#pragma unroll
            for (int i = 0; i < 4; i++) a[i] = xs[(sgp * 4 + i) * 33 + c];
#pragma unroll
            for (int k = 0; k < 8; k++) bb[k] = ads[(jg * 8 + k) * 33 + c];
#pragma unroll
            for (int i = 0; i < 4; i++)
#pragma unroll
                for (int k = 0; k < 8; k++) accL[i][k] += a[i] * bb[k];
        }
    }
    __syncthreads();
#pragma unroll
    for (int i = 0; i < 4; i++)
#pragma unroll
        for (int k = 0; k < 8; k++)
            Ls[(sgp * 4 + i) * 64 + jg * 8 + k] = accL[i][k] * TINV;

    int lane = tid & 31, w = tid >> 5;
    for (int rr = 0; rr < 16; rr++) {
        int r = w * 16 + rr, sgl = s0 + r;
        unsigned long long bk = best[b * 1024 + sgl];
        int ind = (int)(0xFFFFFFFFu - (uint32_t)(bk & 0xFFFFFFFFull));
        float sum = 0.0f;
#pragma unroll
        for (int c = lane; c < 128; c += 32)
            sum += xA[(size_t)sgl * 128 + c] * xB[(size_t)ind * 128 + c];
#pragma unroll
        for (int off = 16; off; off >>= 1) sum += __shfl_xor_sync(0xFFFFFFFFu, sum, off);
        if (lane == 0) posv[r] = sum * TINV;
    }
    __syncthreads();

    float wsum = 0.0f;
    for (int rr = 0; rr < 16; rr++) {
        int r = w * 16 + rr;
        float v0 = Ls[r * 64 + lane], v1 = Ls[r * 64 + lane + 32];
        if (lane == b) v0 = -1e30f;
        if (lane + 32 == b) v1 = -1e30f;
        float pos = posv[r];
        float mx = fmaxf(fmaxf(v0, v1), pos);
#pragma unroll
        for (int off = 16; off; off >>= 1) mx = fmaxf(mx, __shfl_xor_sync(0xFFFFFFFFu, mx, off));
        float e = expf(v0 - mx) + expf(v1 - mx);
#pragma unroll
        for (int off = 16; off; off >>= 1) e += __shfl_xor_sync(0xFFFFFFFFu, e, off);
        if (lane == 0) wsum += logf(e + expf(pos - mx)) + mx - pos;
    }
    if (lane == 0) atomicAdd(&d_dsum, (double)wsum);
}

__global__ void k_final(const int* __restrict__ epoch, float* __restrict__ out) {
    float g = (float)(d_gsum / 128.0);
    float d = (float)(d_dsum / 131072.0);
    out[0] = (*epoch > 0) ? (0.5f * g + 0.5f * d) : g;
}

extern "C" void kernel_launch(void* const* d_in, const int* in_sizes, int n_in,
                              void* d_out, int out_size) {
    const float* ofq = (const float*)d_in[0];
    const float* agq = (const float*)d_in[1];
    const float* xq  = (const float*)d_in[2];
    const float* adq = (const float*)d_in[3];
    const float* ofk = (const float*)d_in[4];
    const float* agk = (const float*)d_in[5];
    const float* xk  = (const float*)d_in[6];
    const float* adk = (const float*)d_in[7];
    const int* epoch = (const int*)d_in[8];
    float* out = (float*)d_out;

    static int attr_done = 0;
    if (!attr_done) {
        cudaFuncSetAttribute(k_simargmax, cudaFuncAttributeMaxDynamicSharedMemorySize, SIM_SMEM);
        attr_done = 1;
    }

    k_init<<<256, 256>>>();
    k_agn<<<128, 128>>>(agq, agk);
    k_global<<<128, 128>>>();
    k_prep_of<<<dim3(32, 128), 256>>>(ofq, ofk);
    k_prep_x<<<dim3(32, 128), 256>>>(xq, xk);
    k_simargmax<<<dim3(8, 8, 64), 256, SIM_SMEM>>>();
    k_dense<<<dim3(8, 64, 2), 256>>>(adq, adk);
    k_final<<<1, 1>>>(epoch, out);
}

// round 5
// speedup vs baseline: 1.0622x; 1.0622x over previous
#include <cuda_runtime.h>
#include <cuda_bf16.h>
#include <stdint.h>

#define TINV 10.0f

__device__ float d_agn[128 * 128];
__device__ float d_ofinv[128 * 1024];
__device__ __nv_bfloat16 d_ofh[128ull * 1024 * 256]; // [bb][s][d] bf16; bb: q 0-63, k 64-127
__device__ float d_xn[2][64 * 1024 * 128];           // normalized x, [b][s][c]
__device__ unsigned long long d_rowbest[64 * 1024];
__device__ unsigned long long d_colbest[64 * 1024];
__device__ double d_gsum, d_dsum;

// ---------------- helpers ----------------
__device__ __forceinline__ uint32_t smem_u32(const void* p) {
    uint32_t a;
    asm("{ .reg .u64 t; cvta.to.shared.u64 t, %1; cvt.u32.u64 %0, t; }" : "=r"(a) : "l"(p));
    return a;
}
__device__ __forceinline__ uint32_t fkey(float f) {
    uint32_t u = __float_as_uint(f);
    return (u & 0x80000000u) ? ~u : (u | 0x80000000u);
}
__device__ __forceinline__ unsigned long long packkey(float v, uint32_t idx) {
    return ((unsigned long long)fkey(v) << 32) | (unsigned long long)(0xFFFFFFFFu - idx);
}
__device__ __forceinline__ unsigned long long shflx64(unsigned long long v, int m) {
    return __shfl_xor_sync(0xFFFFFFFFu, v, m);
}
__device__ __forceinline__ void cp16(uint32_t dst, const void* src) {
    asm volatile("cp.async.cg.shared.global [%0],[%1],16;\n" :: "r"(dst), "l"(src));
}
#define CP_COMMIT() asm volatile("cp.async.commit_group;\n" ::: "memory")
__device__ __forceinline__ void ldsm4(uint32_t& r0, uint32_t& r1, uint32_t& r2,
                                      uint32_t& r3, uint32_t a) {
    asm volatile("ldmatrix.sync.aligned.m8n8.x4.shared.b16 {%0,%1,%2,%3},[%4];\n"
                 : "=r"(r0), "=r"(r1), "=r"(r2), "=r"(r3) : "r"(a));
}
__device__ __forceinline__ void mma16816(float* c, const uint32_t* a, const uint32_t* b) {
    asm volatile("mma.sync.aligned.m16n8k16.row.col.f32.bf16.bf16.f32 "
                 "{%0,%1,%2,%3},{%4,%5,%6,%7},{%8,%9},{%0,%1,%2,%3};\n"
                 : "+f"(c[0]), "+f"(c[1]), "+f"(c[2]), "+f"(c[3])
                 : "r"(a[0]), "r"(a[1]), "r"(a[2]), "r"(a[3]), "r"(b[0]), "r"(b[1]));
}

// ---------------- K0: init ----------------
__global__ void k_init() {
    int i = blockIdx.x * blockDim.x + threadIdx.x;
    if (i < 64 * 1024) { d_rowbest[i] = 0ULL; d_colbest[i] = 0ULL; }
    if (i == 0) { d_gsum = 0.0; d_dsum = 0.0; }
}

// ---------------- global loss ----------------
__global__ void k_agn(const float* __restrict__ agq, const float* __restrict__ agk) {
    int row = blockIdx.x, c = threadIdx.x;
    const float* src = (row < 64) ? (agq + row * 128) : (agk + (row - 64) * 128);
    float v = src[c];
    __shared__ float red[128];
    red[c] = v * v; __syncthreads();
    for (int off = 64; off; off >>= 1) { if (c < off) red[c] += red[c + off]; __syncthreads(); }
    d_agn[row * 128 + c] = v / fmaxf(sqrtf(red[0]), 1e-12f);
}
__global__ void k_global() {
    int i = blockIdx.x, j = threadIdx.x;
    __shared__ float ai[128], red[128], s_pos;
    ai[j] = d_agn[i * 128 + j];
    __syncthreads();
    float dot = 0.0f;
#pragma unroll 8
    for (int c = 0; c < 128; c++) dot += ai[c] * d_agn[j * 128 + c];
    float lg = dot * TINV;
    if (j == ((i + 64) & 127)) s_pos = lg;
    float v = (j == i) ? -1e30f : lg;
    red[j] = v; __syncthreads();
    for (int off = 64; off; off >>= 1) { if (j < off) red[j] = fmaxf(red[j], red[j + off]); __syncthreads(); }
    float mx = red[0]; __syncthreads();
    red[j] = expf(v - mx); __syncthreads();
    for (int off = 64; off; off >>= 1) { if (j < off) red[j] += red[j + off]; __syncthreads(); }
    if (j == 0) atomicAdd(&d_gsum, (double)(logf(red[0]) + mx - s_pos));
}

// ---------------- of: transpose -> [s][d] bf16 + col inv-norms ----------------
__global__ void __launch_bounds__(256) k_prep_of(const float* __restrict__ ofq,
                                                 const float* __restrict__ ofk) {
    __shared__ float sh[32 * 257];
    int bb = blockIdx.y, s0 = blockIdx.x * 32, tid = threadIdx.x;
    const float* p = (bb < 64 ? ofq : ofk) + (size_t)(bb & 63) * 256 * 1024;
#pragma unroll 8
    for (int it = 0; it < 32; it++) {
        int idx = it * 256 + tid, dd = idx >> 5, s = idx & 31;
        sh[s * 257 + dd] = p[(size_t)dd * 1024 + s0 + s];
    }
    __syncthreads();
    int s = tid >> 3, part = tid & 7, d0 = part * 32;
    const float* row = &sh[s * 257 + d0];
    float acc = 0.0f;
    uint32_t pk[16];
#pragma unroll
    for (int ii = 0; ii < 16; ii++) {
        int i = (ii + part * 2) & 15;  // stagger -> conflict-free
        float a = row[2 * i], b2 = row[2 * i + 1];
        acc += a * a + b2 * b2;
        __nv_bfloat162 h = __floats2bfloat162_rn(a, b2);
        pk[i] = *reinterpret_cast<uint32_t*>(&h);
    }
    acc += __shfl_xor_sync(0xFFFFFFFFu, acc, 1);
    acc += __shfl_xor_sync(0xFFFFFFFFu, acc, 2);
    acc += __shfl_xor_sync(0xFFFFFFFFu, acc, 4);
    if (part == 0) d_ofinv[bb * 1024 + s0 + s] = 1.0f / fmaxf(sqrtf(acc), 1e-12f);
    uint4* dst = (uint4*)(d_ofh + ((size_t)bb * 1024 + s0 + s) * 256 + d0);
#pragma unroll
    for (int q = 0; q < 4; q++)
        dst[q] = make_uint4(pk[q * 4], pk[q * 4 + 1], pk[q * 4 + 2], pk[q * 4 + 3]);
}

// ---------------- x: normalize over C + transpose ----------------
__global__ void k_prep_x(const float* __restrict__ xq, const float* __restrict__ xk) {
    __shared__ float sh[128 * 33];
    __shared__ float invs[32];
    int bb = blockIdx.y, s0 = blockIdx.x * 32, tid = threadIdx.x;
    const float* src = (bb < 64 ? xq : xk) + (size_t)(bb & 63) * 128 * 1024;
    float* dst = d_xn[bb < 64 ? 0 : 1] + (size_t)(bb & 63) * 1024 * 128;
#pragma unroll
    for (int it = 0; it < 16; it++) {
        int idx = it * 256 + tid, c = idx >> 5, s = idx & 31;
        sh[c * 33 + s] = src[(size_t)c * 1024 + s0 + s];
    }
    __syncthreads();
    if (tid < 32) {
        float acc = 0.0f;
#pragma unroll 8
        for (int c = 0; c < 128; c++) { float v = sh[c * 33 + tid]; acc += v * v; }
        invs[tid] = 1.0f / fmaxf(sqrtf(acc), 1e-12f);
    }
    __syncthreads();
#pragma unroll
    for (int it = 0; it < 16; it++) {
        int idx = it * 256 + tid, s = idx >> 7, c = idx & 127;
        dst[(size_t)(s0 + s) * 128 + c] = sh[c * 33 + s] * invs[s];
    }
}

// ---------------- sim GEMM (bf16 mma, pipelined) + fused dual argmax ----------------
// CTA tile 128(s) x 256(t), K=256 fully resident. 8 warps of 64x64. 192KB dyn smem.
#define SIM_SMEM 196608
__global__ void __launch_bounds__(256, 1) k_simargmax() {
    extern __shared__ __align__(16) char dsm[];
    __shared__ float qf[128], kf[256];
    __shared__ unsigned long long s_row[128], s_col[256];
    int tid = threadIdx.x, lane = tid & 31, wid = tid >> 5;
    int b = blockIdx.z, s0 = blockIdx.y * 128, t0 = blockIdx.x * 256;
    const char* Aq = (const char*)(d_ofh + ((size_t)b * 1024 + s0) * 256);
    const char* Bq = (const char*)(d_ofh + ((size_t)(64 + b) * 1024 + t0) * 256);

    if (tid < 128) { qf[tid] = d_ofinv[b * 1024 + s0 + tid]; s_row[tid] = 0ULL; }
    kf[tid] = d_ofinv[(64 + b) * 1024 + t0 + tid];
    s_col[tid] = 0ULL;

    uint32_t a_base = smem_u32(dsm), b_base = a_base + 65536;
    // issue all loads: 4 commit groups of K-64 each (A rows 512B, swizzled 16B units)
#pragma unroll
    for (int c = 0; c < 4; c++) {
#pragma unroll
        for (int it = 0; it < 4; it++) {
            int idx = it * 256 + tid;
            int row = idx >> 3, u8 = idx & 7;
            cp16(a_base + (uint32_t)row * 512 + (uint32_t)((c * 8 + (u8 ^ (row & 7))) << 4),
                 Aq + (size_t)row * 512 + c * 128 + u8 * 16);
        }
#pragma unroll
        for (int it = 0; it < 8; it++) {
            int idx = it * 256 + tid;
            int row = idx >> 3, u8 = idx & 7;
            cp16(b_base + (uint32_t)row * 512 + (uint32_t)((c * 8 + (u8 ^ (row & 7))) << 4),
                 Bq + (size_t)row * 512 + c * 128 + u8 * 16);
        }
        CP_COMMIT();
    }

    int wm = wid & 1, wn = wid >> 1;            // warp tile: rows wm*64, cols wn*64
    int row_in = lane & 15, ub = lane >> 4;
    float acc[4][8][4];
#pragma unroll
    for (int mi = 0; mi < 4; mi++)
#pragma unroll
        for (int ni = 0; ni < 8; ni++)
#pragma unroll
            for (int r = 0; r < 4; r++) acc[mi][ni][r] = 0.0f;

#define DO_CHUNK(C, W) do { \
    asm volatile("cp.async.wait_group %0;\n" :: "n"(W) : "memory"); \
    __syncthreads(); \
    _Pragma("unroll") \
    for (int ks = 0; ks < 4; ks++) { \
        int ubase = (C) * 8 + ks * 2 + ub; \
        uint32_t af[4][4], bfr[8][2]; \
        _Pragma("unroll") \
        for (int mi = 0; mi < 4; mi++) { \
            int r = wm * 64 + mi * 16 + row_in; \
            ldsm4(af[mi][0], af[mi][1], af[mi][2], af[mi][3], \
                  a_base + (uint32_t)r * 512 + (uint32_t)(((ubase & ~7) + ((ubase & 7) ^ (r & 7))) << 4)); \
        } \
        _Pragma("unroll") \
        for (int np = 0; np < 4; np++) { \
            int r = wn * 64 + np * 16 + row_in; \
            uint32_t r0, r1, r2, r3; \
            ldsm4(r0, r1, r2, r3, \
                  b_base + (uint32_t)r * 512 + (uint32_t)(((ubase & ~7) + ((ubase & 7) ^ (r & 7))) << 4)); \
            bfr[np * 2][0] = r0; bfr[np * 2][1] = r2; \
            bfr[np * 2 + 1][0] = r1; bfr[np * 2 + 1][1] = r3; \
        } \
        _Pragma("unroll") \
        for (int mi = 0; mi < 4; mi++) \
            _Pragma("unroll") \
            for (int ni = 0; ni < 8; ni++) \
                mma16816(acc[mi][ni], af[mi], bfr[ni]); \
    } } while (0)

    DO_CHUNK(0, 3);
    DO_CHUNK(1, 2);
    DO_CHUNK(2, 1);
    DO_CHUNK(3, 0);
#undef DO_CHUNK

    int g = lane >> 2, tg = lane & 3;
    // row argmax (over t): weight kf[t]
#pragma unroll
    for (int mi = 0; mi < 4; mi++)
#pragma unroll
        for (int rh = 0; rh < 2; rh++) {
            unsigned long long best = 0ULL;
#pragma unroll
            for (int ni = 0; ni < 8; ni++)
#pragma unroll
                for (int cp = 0; cp < 2; cp++) {
                    int tl = wn * 64 + ni * 8 + 2 * tg + cp;
                    unsigned long long k2 =
                        packkey(acc[mi][ni][rh * 2 + cp] * kf[tl], (uint32_t)(t0 + tl));
                    best = (k2 > best) ? k2 : best;
                }
            unsigned long long o;
            o = shflx64(best, 1); best = (o > best) ? o : best;
            o = shflx64(best, 2); best = (o > best) ? o : best;
            if (tg == 0)
                atomicMax(&s_row[wm * 64 + mi * 16 + g + 8 * rh], best);
        }
    // col argmax (over s): weight qf[s]
#pragma unroll
    for (int ni = 0; ni < 8; ni++)
#pragma unroll
        for (int cp = 0; cp < 2; cp++) {
            int tl = wn * 64 + ni * 8 + 2 * tg + cp;
            unsigned long long best = 0ULL;
#pragma unroll
            for (int mi = 0; mi < 4; mi++)
#pragma unroll
                for (int rh = 0; rh < 2; rh++) {
                    int sl = wm * 64 + mi * 16 + g + 8 * rh;
                    unsigned long long k2 =
                        packkey(acc[mi][ni][rh * 2 + cp] * qf[sl], (uint32_t)(s0 + sl));
                    best = (k2 > best) ? k2 : best;
                }
            unsigned long long o;
            o = shflx64(best, 4);  best = (o > best) ? o : best;
            o = shflx64(best, 8);  best = (o > best) ? o : best;
            o = shflx64(best, 16); best = (o > best) ? o : best;
            if (g == 0) atomicMax(&s_col[tl], best);
        }
    __syncthreads();
    if (tid < 128) atomicMax(&d_rowbest[(size_t)b * 1024 + s0 + tid], s_row[tid]);
    atomicMax(&d_colbest[(size_t)b * 1024 + t0 + tid], s_col[tid]);
}

// ---------------- dense losses ----------------
__global__ void __launch_bounds__(256) k_dense(const float* __restrict__ adq,
                                               const float* __restrict__ adk) {
    int b = blockIdx.y, dir = blockIdx.z, s0 = blockIdx.x * 128;
    const float* xA = d_xn[dir] + (size_t)b * 1024 * 128;
    const float* xB = d_xn[dir ^ 1] + (size_t)b * 1024 * 128;
    const float* ad = dir ? adq : adk;
    const unsigned long long* best = dir ? d_colbest : d_rowbest;

    __shared__ __align__(16) float sbuf[128 * 64 + 128];
    float* Ls = sbuf;
    float* posv = sbuf + 128 * 64;
    float* xs = sbuf;
    float* ads = sbuf + 128 * 33;

    int tid = threadIdx.x, sgp = tid >> 3, jg = tid & 7;
    float accL[4][8];
#pragma unroll
    for (int i = 0; i < 4; i++)
#pragma unroll
        for (int k = 0; k < 8; k++) accL[i][k] = 0.0f;

    for (int cc = 0; cc < 4; cc++) {
        __syncthreads();
        int c0 = cc * 32;
#pragma unroll
        for (int it = 0; it < 16; it++) {
            int idx = it * 256 + tid, r = idx >> 5, c = idx & 31;
            xs[r * 33 + c] = xA[(size_t)(s0 + r) * 128 + c0 + c];
        }
#pragma unroll
        for (int it = 0; it < 8; it++) {
            int idx = it * 256 + tid, j = idx >> 5, c = idx & 31;
            ads[j * 33 + c] = ad[j * 128 + c0 + c];
        }
        __syncthreads();
#pragma unroll 4
        for (int c = 0; c < 32; c++) {
            float a[4], bb[8];
#pragma unroll
            for (int i = 0; i < 4; i++) a[i] = xs[(sgp * 4 + i) * 33 + c];
#pragma unroll
            for (int k = 0; k < 8; k++) bb[k] = ads[(jg * 8 + k) * 33 + c];
#pragma unroll
            for (int i = 0; i < 4; i++)
#pragma unroll
                for (int k = 0; k < 8; k++) accL[i][k] += a[i] * bb[k];
        }
    }
    __syncthreads();
#pragma unroll
    for (int i = 0; i < 4; i++)
#pragma unroll
        for (int k = 0; k < 8; k++)
            Ls[(sgp * 4 + i) * 64 + jg * 8 + k] = accL[i][k] * TINV;

    int lane = tid & 31, w = tid >> 5;
    for (int rr = 0; rr < 16; rr++) {
        int r = w * 16 + rr, sgl = s0 + r;
        unsigned long long bk = best[b * 1024 + sgl];
        int ind = (int)(0xFFFFFFFFu - (uint32_t)(bk & 0xFFFFFFFFull));
        float sum = 0.0f;
#pragma unroll
        for (int c = lane; c < 128; c += 32)
            sum += xA[(size_t)sgl * 128 + c] * xB[(size_t)ind * 128 + c];
#pragma unroll
        for (int off = 16; off; off >>= 1) sum += __shfl_xor_sync(0xFFFFFFFFu, sum, off);
        if (lane == 0) posv[r] = sum * TINV;
    }
    __syncthreads();

    float wsum = 0.0f;
    for (int rr = 0; rr < 16; rr++) {
        int r = w * 16 + rr;
        float v0 = Ls[r * 64 + lane], v1 = Ls[r * 64 + lane + 32];
        if (lane == b) v0 = -1e30f;
        if (lane + 32 == b) v1 = -1e30f;
        float pos = posv[r];
        float mx = fmaxf(fmaxf(v0, v1), pos);
#pragma unroll
        for (int off = 16; off; off >>= 1) mx = fmaxf(mx, __shfl_xor_sync(0xFFFFFFFFu, mx, off));
        float e = expf(v0 - mx) + expf(v1 - mx);
#pragma unroll
        for (int off = 16; off; off >>= 1) e += __shfl_xor_sync(0xFFFFFFFFu, e, off);
        if (lane == 0) wsum += logf(e + expf(pos - mx)) + mx - pos;
    }
    if (lane == 0) atomicAdd(&d_dsum, (double)wsum);
}

__global__ void k_final(const int* __restrict__ epoch, float* __restrict__ out) {
    float g = (float)(d_gsum / 128.0);
    float d = (float)(d_dsum / 131072.0);
    out[0] = (*epoch > 0) ? (0.5f * g + 0.5f * d) : g;
}

extern "C" void kernel_launch(void* const* d_in, const int* in_sizes, int n_in,
                              void* d_out, int out_size) {
    const float* ofq = (const float*)d_in[0];
    const float* agq = (const float*)d_in[1];
    const float* xq  = (const float*)d_in[2];
    const float* adq = (const float*)d_in[3];
    const float* ofk = (const float*)d_in[4];
    const float* agk = (const float*)d_in[5];
    const float* xk  = (const float*)d_in[6];
    const float* adk = (const float*)d_in[7];
    const int* epoch = (const int*)d_in[8];
    float* out = (float*)d_out;

    cudaFuncSetAttribute(k_simargmax, cudaFuncAttributeMaxDynamicSharedMemorySize, SIM_SMEM);

    k_init<<<256, 256>>>();
    k_agn<<<128, 128>>>(agq, agk);
    k_global<<<128, 128>>>();
    k_prep_of<<<dim3(32, 128), 256>>>(ofq, ofk);
    k_prep_x<<<dim3(32, 128), 256>>>(xq, xk);
    k_simargmax<<<dim3(4, 8, 64), 256, SIM_SMEM>>>();
    k_dense<<<dim3(8, 64, 2), 256>>>(adq, adk);
    k_final<<<1, 1>>>(epoch, out);
}

// round 6
// speedup vs baseline: 1.2140x; 1.1429x over previous
#include <cuda_runtime.h>
#include <cuda_fp16.h>
#include <stdint.h>

#define TINV 10.0f

__device__ float d_agn[128 * 128];
__device__ float d_ofinv[128 * 1024];
__device__ __half d_ofh[128ull * 1024 * 256];  // [bb][s][d] f16; bb: q 0-63, k 64-127
__device__ float d_xn[2][64 * 1024 * 128];     // normalized x, [b][s][c]
__device__ unsigned long long d_rowbest[64 * 1024];
__device__ unsigned long long d_colbest[64 * 1024];
__device__ double d_gsum, d_dsum;

// ---------------- helpers ----------------
__device__ __forceinline__ uint32_t smem_u32(const void* p) {
    uint32_t a;
    asm("{ .reg .u64 t; cvta.to.shared.u64 t, %1; cvt.u32.u64 %0, t; }" : "=r"(a) : "l"(p));
    return a;
}
__device__ __forceinline__ uint32_t fkey(float f) {
    uint32_t u = __float_as_uint(f);
    return (u & 0x80000000u) ? ~u : (u | 0x80000000u);
}
__device__ __forceinline__ unsigned long long packkey(float v, uint32_t idx) {
    return ((unsigned long long)fkey(v) << 32) | (unsigned long long)(0xFFFFFFFFu - idx);
}
__device__ __forceinline__ unsigned long long shflx64(unsigned long long v, int m) {
    return __shfl_xor_sync(0xFFFFFFFFu, v, m);
}
__device__ __forceinline__ void cp16(uint32_t dst, const void* src) {
    asm volatile("cp.async.cg.shared.global [%0],[%1],16;\n" :: "r"(dst), "l"(src));
}
#define CP_COMMIT() asm volatile("cp.async.commit_group;\n" ::: "memory")
__device__ __forceinline__ void ldsm4(uint32_t& r0, uint32_t& r1, uint32_t& r2,
                                      uint32_t& r3, uint32_t a) {
    asm volatile("ldmatrix.sync.aligned.m8n8.x4.shared.b16 {%0,%1,%2,%3},[%4];\n"
                 : "=r"(r0), "=r"(r1), "=r"(r2), "=r"(r3) : "r"(a));
}
// f16 accumulate: D = {2 x u32} of half2
__device__ __forceinline__ void mma16816h(uint32_t* c, const uint32_t* a, const uint32_t* b) {
    asm volatile("mma.sync.aligned.m16n8k16.row.col.f16.f16.f16.f16 "
                 "{%0,%1},{%2,%3,%4,%5},{%6,%7},{%0,%1};\n"
                 : "+r"(c[0]), "+r"(c[1])
                 : "r"(a[0]), "r"(a[1]), "r"(a[2]), "r"(a[3]), "r"(b[0]), "r"(b[1]));
}

// ---------------- K0: init ----------------
__global__ void k_init() {
    int i = blockIdx.x * blockDim.x + threadIdx.x;
    if (i < 64 * 1024) { d_rowbest[i] = 0ULL; d_colbest[i] = 0ULL; }
    if (i == 0) { d_gsum = 0.0; d_dsum = 0.0; }
}

// ---------------- global loss ----------------
__global__ void k_agn(const float* __restrict__ agq, const float* __restrict__ agk) {
    int row = blockIdx.x, c = threadIdx.x;
    const float* src = (row < 64) ? (agq + row * 128) : (agk + (row - 64) * 128);
    float v = src[c];
    __shared__ float red[128];
    red[c] = v * v; __syncthreads();
    for (int off = 64; off; off >>= 1) { if (c < off) red[c] += red[c + off]; __syncthreads(); }
    d_agn[row * 128 + c] = v / fmaxf(sqrtf(red[0]), 1e-12f);
}
__global__ void k_global() {
    int i = blockIdx.x, j = threadIdx.x;
    __shared__ float ai[128], red[128], s_pos;
    ai[j] = d_agn[i * 128 + j];
    __syncthreads();
    float dot = 0.0f;
#pragma unroll 8
    for (int c = 0; c < 128; c++) dot += ai[c] * d_agn[j * 128 + c];
    float lg = dot * TINV;
    if (j == ((i + 64) & 127)) s_pos = lg;
    float v = (j == i) ? -1e30f : lg;
    red[j] = v; __syncthreads();
    for (int off = 64; off; off >>= 1) { if (j < off) red[j] = fmaxf(red[j], red[j + off]); __syncthreads(); }
    float mx = red[0]; __syncthreads();
    red[j] = expf(v - mx); __syncthreads();
    for (int off = 64; off; off >>= 1) { if (j < off) red[j] += red[j + off]; __syncthreads(); }
    if (j == 0) atomicAdd(&d_gsum, (double)(logf(red[0]) + mx - s_pos));
}

// ---------------- of: transpose -> [s][d] f16 + col inv-norms ----------------
__global__ void __launch_bounds__(256) k_prep_of(const float* __restrict__ ofq,
                                                 const float* __restrict__ ofk) {
    __shared__ float sh[32 * 257];
    int bb = blockIdx.y, s0 = blockIdx.x * 32, tid = threadIdx.x;
    const float* p = (bb < 64 ? ofq : ofk) + (size_t)(bb & 63) * 256 * 1024;
#pragma unroll 8
    for (int it = 0; it < 32; it++) {
        int idx = it * 256 + tid, dd = idx >> 5, s = idx & 31;
        sh[s * 257 + dd] = p[(size_t)dd * 1024 + s0 + s];
    }
    __syncthreads();
    int s = tid >> 3, part = tid & 7, d0 = part * 32;
    const float* row = &sh[s * 257 + d0];
    float acc = 0.0f;
    uint32_t pk[16];
#pragma unroll
    for (int ii = 0; ii < 16; ii++) {
        int i = (ii + part * 2) & 15;  // stagger -> conflict-free
        float a = row[2 * i], b2 = row[2 * i + 1];
        acc += a * a + b2 * b2;
        __half2 h = __floats2half2_rn(a, b2);
        pk[i] = *reinterpret_cast<uint32_t*>(&h);
    }
    acc += __shfl_xor_sync(0xFFFFFFFFu, acc, 1);
    acc += __shfl_xor_sync(0xFFFFFFFFu, acc, 2);
    acc += __shfl_xor_sync(0xFFFFFFFFu, acc, 4);
    if (part == 0) d_ofinv[bb * 1024 + s0 + s] = 1.0f / fmaxf(sqrtf(acc), 1e-12f);
    uint4* dst = (uint4*)(d_ofh + ((size_t)bb * 1024 + s0 + s) * 256 + d0);
#pragma unroll
    for (int q = 0; q < 4; q++)
        dst[q] = make_uint4(pk[q * 4], pk[q * 4 + 1], pk[q * 4 + 2], pk[q * 4 + 3]);
}

// ---------------- x: normalize over C + transpose ----------------
__global__ void k_prep_x(const float* __restrict__ xq, const float* __restrict__ xk) {
    __shared__ float sh[128 * 33];
    __shared__ float invs[32];
    int bb = blockIdx.y, s0 = blockIdx.x * 32, tid = threadIdx.x;
    const float* src = (bb < 64 ? xq : xk) + (size_t)(bb & 63) * 128 * 1024;
    float* dst = d_xn[bb < 64 ? 0 : 1] + (size_t)(bb & 63) * 1024 * 128;
#pragma unroll
    for (int it = 0; it < 16; it++) {
        int idx = it * 256 + tid, c = idx >> 5, s = idx & 31;
        sh[c * 33 + s] = src[(size_t)c * 1024 + s0 + s];
    }
    __syncthreads();
    if (tid < 32) {
        float acc = 0.0f;
#pragma unroll 8
        for (int c = 0; c < 128; c++) { float v = sh[c * 33 + tid]; acc += v * v; }
        invs[tid] = 1.0f / fmaxf(sqrtf(acc), 1e-12f);
    }
    __syncthreads();
#pragma unroll
    for (int it = 0; it < 16; it++) {
        int idx = it * 256 + tid, s = idx >> 7, c = idx & 127;
        dst[(size_t)(s0 + s) * 128 + c] = sh[c * 33 + s] * invs[s];
    }
}

// ---------------- sim GEMM (f16 mma, f16 acc, 2-stage pipeline) + dual argmax ----
// CTA 128(s) x 256(t), K chunks of 64, 2 stages (96KB), 2 CTAs/SM. 8 warps 64x64.
#define SIM_SMEM 98304
__global__ void __launch_bounds__(256, 2) k_simargmax() {
    extern __shared__ __align__(16) char dsm[];
    __shared__ float qf[128], kf[256];
    __shared__ unsigned long long s_row[128], s_col[256];
    int tid = threadIdx.x, lane = tid & 31, wid = tid >> 5;
    int b = blockIdx.z, s0 = blockIdx.y * 128, t0 = blockIdx.x * 256;
    const char* Aq = (const char*)(d_ofh + ((size_t)b * 1024 + s0) * 256);
    const char* Bq = (const char*)(d_ofh + ((size_t)(64 + b) * 1024 + t0) * 256);

    if (tid < 128) { qf[tid] = d_ofinv[b * 1024 + s0 + tid]; s_row[tid] = 0ULL; }
    kf[tid] = d_ofinv[(64 + b) * 1024 + t0 + tid];
    s_col[tid] = 0ULL;

    uint32_t base = smem_u32(dsm);

    // chunk rows are 128B = 8 x 16B units; swizzle u ^ (row&7)
#define LOAD_CHUNK(c, st) do { \
    uint32_t ab = base + (st) * 49152, bb2 = ab + 16384; \
    _Pragma("unroll") \
    for (int it = 0; it < 4; it++) { \
        int idx = it * 256 + tid, row = idx >> 3, u = idx & 7; \
        cp16(ab + (uint32_t)row * 128 + (uint32_t)((u ^ (row & 7)) << 4), \
             Aq + (size_t)row * 512 + (c) * 128 + u * 16); \
    } \
    _Pragma("unroll") \
    for (int it = 0; it < 8; it++) { \
        int idx = it * 256 + tid, row = idx >> 3, u = idx & 7; \
        cp16(bb2 + (uint32_t)row * 128 + (uint32_t)((u ^ (row & 7)) << 4), \
             Bq + (size_t)row * 512 + (c) * 128 + u * 16); \
    } \
    CP_COMMIT(); } while (0)

    LOAD_CHUNK(0, 0);
    LOAD_CHUNK(1, 1);

    int wm = wid & 1, wn = wid >> 1;  // warp tile rows wm*64, cols wn*64
    int row_in = lane & 15, ub = lane >> 4;
    uint32_t acc[4][8][2];
#pragma unroll
    for (int mi = 0; mi < 4; mi++)
#pragma unroll
        for (int ni = 0; ni < 8; ni++) { acc[mi][ni][0] = 0u; acc[mi][ni][1] = 0u; }

#define DO_CHUNK(C, W) do { \
    asm volatile("cp.async.wait_group %0;\n" :: "n"(W) : "memory"); \
    __syncthreads(); \
    uint32_t ab = base + ((C) & 1) * 49152, bb2 = ab + 16384; \
    _Pragma("unroll") \
    for (int ks = 0; ks < 4; ks++) { \
        int u = ks * 2 + ub; \
        uint32_t af[4][4], bfr[8][2]; \
        _Pragma("unroll") \
        for (int mi = 0; mi < 4; mi++) { \
            int r = wm * 64 + mi * 16 + row_in; \
            ldsm4(af[mi][0], af[mi][1], af[mi][2], af[mi][3], \
                  ab + (uint32_t)r * 128 + (uint32_t)((u ^ (r & 7)) << 4)); \
        } \
        _Pragma("unroll") \
        for (int np = 0; np < 4; np++) { \
            int r = wn * 64 + np * 16 + row_in; \
            uint32_t r0, r1, r2, r3; \
            ldsm4(r0, r1, r2, r3, \
                  bb2 + (uint32_t)r * 128 + (uint32_t)((u ^ (r & 7)) << 4)); \
            bfr[np * 2][0] = r0; bfr[np * 2][1] = r2; \
            bfr[np * 2 + 1][0] = r1; bfr[np * 2 + 1][1] = r3; \
        } \
        _Pragma("unroll") \
        for (int mi = 0; mi < 4; mi++) \
            _Pragma("unroll") \
            for (int ni = 0; ni < 8; ni++) \
                mma16816h(acc[mi][ni], af[mi], bfr[ni]); \
    } \
    if ((C) < 2) { __syncthreads(); LOAD_CHUNK((C) + 2, (C) & 1); } } while (0)

    DO_CHUNK(0, 1);
    DO_CHUNK(1, 1);
    DO_CHUNK(2, 1);
    DO_CHUNK(3, 0);
#undef DO_CHUNK
#undef LOAD_CHUNK

    int g = lane >> 2, tg = lane & 3;
    // row argmax (over t): weight kf[t]
#pragma unroll
    for (int mi = 0; mi < 4; mi++)
#pragma unroll
        for (int rh = 0; rh < 2; rh++) {
            unsigned long long best = 0ULL;
#pragma unroll
            for (int ni = 0; ni < 8; ni++) {
                float2 v = __half22float2(*reinterpret_cast<__half2*>(&acc[mi][ni][rh]));
                int tl0 = wn * 64 + ni * 8 + 2 * tg;
                unsigned long long k0 = packkey(v.x * kf[tl0], (uint32_t)(t0 + tl0));
                unsigned long long k1 = packkey(v.y * kf[tl0 + 1], (uint32_t)(t0 + tl0 + 1));
                if (k0 > best) best = k0;
                if (k1 > best) best = k1;
            }
            unsigned long long o;
            o = shflx64(best, 1); best = (o > best) ? o : best;
            o = shflx64(best, 2); best = (o > best) ? o : best;
            if (tg == 0)
                atomicMax(&s_row[wm * 64 + mi * 16 + g + 8 * rh], best);
        }
    // col argmax (over s): weight qf[s]
#pragma unroll
    for (int ni = 0; ni < 8; ni++)
#pragma unroll
        for (int cp = 0; cp < 2; cp++) {
            int tl = wn * 64 + ni * 8 + 2 * tg + cp;
            unsigned long long best = 0ULL;
#pragma unroll
            for (int mi = 0; mi < 4; mi++)
#pragma unroll
                for (int rh = 0; rh < 2; rh++) {
                    __half2 h = *reinterpret_cast<__half2*>(&acc[mi][ni][rh]);
                    float vv = cp ? __high2float(h) : __low2float(h);
                    int sl = wm * 64 + mi * 16 + g + 8 * rh;
                    unsigned long long k2 = packkey(vv * qf[sl], (uint32_t)(s0 + sl));
                    if (k2 > best) best = k2;
                }
            unsigned long long o;
            o = shflx64(best, 4);  best = (o > best) ? o : best;
            o = shflx64(best, 8);  best = (o > best) ? o : best;
            o = shflx64(best, 16); best = (o > best) ? o : best;
            if (g == 0) atomicMax(&s_col[tl], best);
        }
    __syncthreads();
    if (tid < 128) atomicMax(&d_rowbest[(size_t)b * 1024 + s0 + tid], s_row[tid]);
    atomicMax(&d_colbest[(size_t)b * 1024 + t0 + tid], s_col[tid]);
}

// ---------------- dense losses ----------------
__global__ void __launch_bounds__(256) k_dense(const float* __restrict__ adq,
                                               const float* __restrict__ adk) {
    int b = blockIdx.y, dir = blockIdx.z, s0 = blockIdx.x * 128;
    const float* xA = d_xn[dir] + (size_t)b * 1024 * 128;
    const float* xB = d_xn[dir ^ 1] + (size_t)b * 1024 * 128;
    const float* ad = dir ? adq : adk;
    const unsigned long long* best = dir ? d_colbest : d_rowbest;

    __shared__ __align__(16) float sbuf[128 * 64 + 128];
    float* Ls = sbuf;
    float* posv = sbuf + 128 * 64;
    float* xs = sbuf;
    float* ads = sbuf + 128 * 33;

    int tid = threadIdx.x, sgp = tid >> 3, jg = tid & 7;
    float accL[4][8];
#pragma unroll
    for (int i = 0; i < 4; i++)
#pragma unroll
        for (int k = 0; k < 8; k++) accL[i][k] = 0.0f;

    for (int cc = 0; cc < 4; cc++) {
        __syncthreads();
        int c0 = cc * 32;
#pragma unroll
        for (int it = 0; it < 16; it++) {
            int idx = it * 256 + tid, r = idx >> 5, c = idx & 31;
            xs[r * 33 + c] = xA[(size_t)(s0 + r) * 128 + c0 + c];
        }
#pragma unroll
        for (int it = 0; it < 8; it++) {
            int idx = it * 256 + tid, j = idx >> 5, c = idx & 31;
            ads[j * 33 + c] = ad[j * 128 + c0 + c];
        }
        __syncthreads();
#pragma unroll 4
        for (int c = 0; c < 32; c++) {
            float a[4], bb[8];
#pragma unroll
            for (int i = 0; i < 4; i++) a[i] = xs[(sgp * 4 + i) * 33 + c];
#pragma unroll
            for (int k = 0; k < 8; k++) bb[k] = ads[(jg * 8 + k) * 33 + c];
#pragma unroll
            for (int i = 0; i < 4; i++)
#pragma unroll
                for (int k = 0; k < 8; k++) accL[i][k] += a[i] * bb[k];
        }
    }
    __syncthreads();
#pragma unroll
    for (int i = 0; i < 4; i++)
#pragma unroll
        for (int k = 0; k < 8; k++)
            Ls[(sgp * 4 + i) * 64 + jg * 8 + k] = accL[i][k] * TINV;

    int lane = tid & 31, w = tid >> 5;
    for (int rr = 0; rr < 16; rr++) {
        int r = w * 16 + rr, sgl = s0 + r;
        unsigned long long bk = best[b * 1024 + sgl];
        int ind = (int)(0xFFFFFFFFu - (uint32_t)(bk & 0xFFFFFFFFull));
        float sum = 0.0f;
#pragma unroll
        for (int c = lane; c < 128; c += 32)
            sum += xA[(size_t)sgl * 128 + c] * xB[(size_t)ind * 128 + c];
#pragma unroll
        for (int off = 16; off; off >>= 1) sum += __shfl_xor_sync(0xFFFFFFFFu, sum, off);
        if (lane == 0) posv[r] = sum * TINV;
    }
    __syncthreads();

    float wsum = 0.0f;
    for (int rr = 0; rr < 16; rr++) {
        int r = w * 16 + rr;
        float v0 = Ls[r * 64 + lane], v1 = Ls[r * 64 + lane + 32];
        if (lane == b) v0 = -1e30f;
        if (lane + 32 == b) v1 = -1e30f;
        float pos = posv[r];
        float mx = fmaxf(fmaxf(v0, v1), pos);
#pragma unroll
        for (int off = 16; off; off >>= 1) mx = fmaxf(mx, __shfl_xor_sync(0xFFFFFFFFu, mx, off));
        float e = expf(v0 - mx) + expf(v1 - mx);
#pragma unroll
        for (int off = 16; off; off >>= 1) e += __shfl_xor_sync(0xFFFFFFFFu, e, off);
        if (lane == 0) wsum += logf(e + expf(pos - mx)) + mx - pos;
    }
    if (lane == 0) atomicAdd(&d_dsum, (double)wsum);
}

__global__ void k_final(const int* __restrict__ epoch, float* __restrict__ out) {
    float g = (float)(d_gsum / 128.0);
    float d = (float)(d_dsum / 131072.0);
    out[0] = (*epoch > 0) ? (0.5f * g + 0.5f * d) : g;
}

extern "C" void kernel_launch(void* const* d_in, const int* in_sizes, int n_in,
                              void* d_out, int out_size) {
    const float* ofq = (const float*)d_in[0];
    const float* agq = (const float*)d_in[1];
    const float* xq  = (const float*)d_in[2];
    const float* adq = (const float*)d_in[3];
    const float* ofk = (const float*)d_in[4];
    const float* agk = (const float*)d_in[5];
    const float* xk  = (const float*)d_in[6];
    const float* adk = (const float*)d_in[7];
    const int* epoch = (const int*)d_in[8];
    float* out = (float*)d_out;

    cudaFuncSetAttribute(k_simargmax, cudaFuncAttributeMaxDynamicSharedMemorySize, SIM_SMEM);

    k_init<<<256, 256>>>();
    k_agn<<<128, 128>>>(agq, agk);
    k_global<<<128, 128>>>();
    k_prep_of<<<dim3(32, 128), 256>>>(ofq, ofk);
    k_prep_x<<<dim3(32, 128), 256>>>(xq, xk);
    k_simargmax<<<dim3(4, 8, 64), 256, SIM_SMEM>>>();
    k_dense<<<dim3(8, 64, 2), 256>>>(adq, adk);
    k_final<<<1, 1>>>(epoch, out);
}

// round 7
// speedup vs baseline: 1.2976x; 1.0688x over previous
#include <cuda_runtime.h>
#include <cuda_fp16.h>
#include <stdint.h>

#define TINV 10.0f

__device__ float d_agn[128 * 128];
__device__ float d_ofinv[128 * 1024];
__device__ __half d_ofh[128ull * 1024 * 256];  // [bb][s][d] f16; bb: q 0-63, k 64-127
__device__ float d_xn[2][64 * 1024 * 128];     // normalized x, [b][s][c]
__device__ unsigned long long d_rowbest[64 * 1024];
__device__ unsigned long long d_colbest[64 * 1024];
__device__ double d_gsum, d_dsum;

// ---------------- helpers ----------------
__device__ __forceinline__ uint32_t smem_u32(const void* p) {
    uint32_t a;
    asm("{ .reg .u64 t; cvta.to.shared.u64 t, %1; cvt.u32.u64 %0, t; }" : "=r"(a) : "l"(p));
    return a;
}
__device__ __forceinline__ uint32_t fkey(float f) {
    uint32_t u = __float_as_uint(f);
    return (u & 0x80000000u) ? ~u : (u | 0x80000000u);
}
__device__ __forceinline__ unsigned long long packkey(float v, uint32_t idx) {
    return ((unsigned long long)fkey(v) << 32) | (unsigned long long)(0xFFFFFFFFu - idx);
}
__device__ __forceinline__ unsigned long long shflx64(unsigned long long v, int m) {
    return __shfl_xor_sync(0xFFFFFFFFu, v, m);
}
__device__ __forceinline__ void cp16(uint32_t dst, const void* src) {
    asm volatile("cp.async.cg.shared.global [%0],[%1],16;\n" :: "r"(dst), "l"(src));
}
#define CP_COMMIT() asm volatile("cp.async.commit_group;\n" ::: "memory")
__device__ __forceinline__ void ldsm4(uint32_t& r0, uint32_t& r1, uint32_t& r2,
                                      uint32_t& r3, uint32_t a) {
    asm volatile("ldmatrix.sync.aligned.m8n8.x4.shared.b16 {%0,%1,%2,%3},[%4];\n"
                 : "=r"(r0), "=r"(r1), "=r"(r2), "=r"(r3) : "r"(a));
}
__device__ __forceinline__ void mma16816h(uint32_t* c, const uint32_t* a, const uint32_t* b) {
    asm volatile("mma.sync.aligned.m16n8k16.row.col.f16.f16.f16.f16 "
                 "{%0,%1},{%2,%3,%4,%5},{%6,%7},{%0,%1};\n"
                 : "+r"(c[0]), "+r"(c[1])
                 : "r"(a[0]), "r"(a[1]), "r"(a[2]), "r"(a[3]), "r"(b[0]), "r"(b[1]));
}

// ---------------- agn (+ scratch init folded in) ----------------
__global__ void k_agn(const float* __restrict__ agq, const float* __restrict__ agk) {
    int row = blockIdx.x, c = threadIdx.x;
    // fold init: 128 blocks x 128 threads = 16384 threads; 65536 u64 each array
    int gt = row * 128 + c;
#pragma unroll
    for (int i = 0; i < 4; i++) {
        d_rowbest[gt * 4 + i] = 0ULL;
        d_colbest[gt * 4 + i] = 0ULL;
    }
    if (gt == 0) { d_gsum = 0.0; d_dsum = 0.0; }

    const float* src = (row < 64) ? (agq + row * 128) : (agk + (row - 64) * 128);
    float v = src[c];
    __shared__ float red[128];
    red[c] = v * v; __syncthreads();
    for (int off = 64; off; off >>= 1) { if (c < off) red[c] += red[c + off]; __syncthreads(); }
    d_agn[row * 128 + c] = v / fmaxf(sqrtf(red[0]), 1e-12f);
}
__global__ void k_global() {
    int i = blockIdx.x, j = threadIdx.x;
    __shared__ float ai[128], red[128], s_pos;
    ai[j] = d_agn[i * 128 + j];
    __syncthreads();
    float dot = 0.0f;
#pragma unroll 8
    for (int c = 0; c < 128; c++) dot += ai[c] * d_agn[j * 128 + c];
    float lg = dot * TINV;
    if (j == ((i + 64) & 127)) s_pos = lg;
    float v = (j == i) ? -1e30f : lg;
    red[j] = v; __syncthreads();
    for (int off = 64; off; off >>= 1) { if (j < off) red[j] = fmaxf(red[j], red[j + off]); __syncthreads(); }
    float mx = red[0]; __syncthreads();
    red[j] = expf(v - mx); __syncthreads();
    for (int off = 64; off; off >>= 1) { if (j < off) red[j] += red[j + off]; __syncthreads(); }
    if (j == 0) atomicAdd(&d_gsum, (double)(logf(red[0]) + mx - s_pos));
}

// ---------------- of: transpose -> [s][d] f16 + col inv-norms (float4 loads) ----
__global__ void __launch_bounds__(256) k_prep_of(const float* __restrict__ ofq,
                                                 const float* __restrict__ ofk) {
    __shared__ float sh[32 * 257];
    int bb = blockIdx.y, s0 = blockIdx.x * 32, tid = threadIdx.x;
    const float* p = (bb < 64 ? ofq : ofk) + (size_t)(bb & 63) * 256 * 1024;
#pragma unroll
    for (int it = 0; it < 8; it++) {
        int idx = it * 256 + tid;           // 0..2047: dd = idx>>3, s4 = idx&7
        int dd = idx >> 3, s4 = idx & 7;
        float4 v = *(const float4*)&p[(size_t)dd * 1024 + s0 + s4 * 4];
        sh[(s4 * 4 + 0) * 257 + dd] = v.x;
        sh[(s4 * 4 + 1) * 257 + dd] = v.y;
        sh[(s4 * 4 + 2) * 257 + dd] = v.z;
        sh[(s4 * 4 + 3) * 257 + dd] = v.w;
    }
    __syncthreads();
    int s = tid >> 3, part = tid & 7, d0 = part * 32;
    const float* row = &sh[s * 257 + d0];
    float acc = 0.0f;
    uint32_t pk[16];
#pragma unroll
    for (int ii = 0; ii < 16; ii++) {
        int i = (ii + part * 2) & 15;  // stagger -> conflict-free
        float a = row[2 * i], b2 = row[2 * i + 1];
        acc += a * a + b2 * b2;
        __half2 h = __floats2half2_rn(a, b2);
        pk[i] = *reinterpret_cast<uint32_t*>(&h);
    }
    acc += __shfl_xor_sync(0xFFFFFFFFu, acc, 1);
    acc += __shfl_xor_sync(0xFFFFFFFFu, acc, 2);
    acc += __shfl_xor_sync(0xFFFFFFFFu, acc, 4);
    if (part == 0) d_ofinv[bb * 1024 + s0 + s] = 1.0f / fmaxf(sqrtf(acc), 1e-12f);
    uint4* dst = (uint4*)(d_ofh + ((size_t)bb * 1024 + s0 + s) * 256 + d0);
#pragma unroll
    for (int q = 0; q < 4; q++)
        dst[q] = make_uint4(pk[q * 4], pk[q * 4 + 1], pk[q * 4 + 2], pk[q * 4 + 3]);
}

// ---------------- x: normalize over C + transpose (float4 loads) ----------------
__global__ void __launch_bounds__(256) k_prep_x(const float* __restrict__ xq,
                                                const float* __restrict__ xk) {
    __shared__ float sh[128 * 33];
    __shared__ float invs[32];
    int bb = blockIdx.y, s0 = blockIdx.x * 32, tid = threadIdx.x;
    const float* src = (bb < 64 ? xq : xk) + (size_t)(bb & 63) * 128 * 1024;
    float* dst = d_xn[bb < 64 ? 0 : 1] + (size_t)(bb & 63) * 1024 * 128;
#pragma unroll
    for (int it = 0; it < 4; it++) {
        int idx = it * 256 + tid;           // 0..1023: c = idx>>3, s4 = idx&7
        int c = idx >> 3, s4 = idx & 7;
        float4 v = *(const float4*)&src[(size_t)c * 1024 + s0 + s4 * 4];
        sh[c * 33 + s4 * 4 + 0] = v.x;
        sh[c * 33 + s4 * 4 + 1] = v.y;
        sh[c * 33 + s4 * 4 + 2] = v.z;
        sh[c * 33 + s4 * 4 + 3] = v.w;
    }
    __syncthreads();
    if (tid < 32) {
        float acc = 0.0f;
#pragma unroll 8
        for (int c = 0; c < 128; c++) { float v = sh[c * 33 + tid]; acc += v * v; }
        invs[tid] = 1.0f / fmaxf(sqrtf(acc), 1e-12f);
    }
    __syncthreads();
#pragma unroll
    for (int it = 0; it < 16; it++) {
        int idx = it * 256 + tid, s = idx >> 7, c = idx & 127;
        dst[(size_t)(s0 + s) * 128 + c] = sh[c * 33 + s] * invs[s];
    }
}

// ---------------- sim GEMM (f16 mma, f16 acc, 2-stage pipeline) + dual argmax ----
#define SIM_SMEM 98304
__global__ void __launch_bounds__(256, 2) k_simargmax() {
    extern __shared__ __align__(16) char dsm[];
    __shared__ float qf[128], kf[256];
    __shared__ unsigned long long s_row[128], s_col[256];
    int tid = threadIdx.x, lane = tid & 31, wid = tid >> 5;
    int b = blockIdx.z, s0 = blockIdx.y * 128, t0 = blockIdx.x * 256;
    const char* Aq = (const char*)(d_ofh + ((size_t)b * 1024 + s0) * 256);
    const char* Bq = (const char*)(d_ofh + ((size_t)(64 + b) * 1024 + t0) * 256);

    if (tid < 128) { qf[tid] = d_ofinv[b * 1024 + s0 + tid]; s_row[tid] = 0ULL; }
    kf[tid] = d_ofinv[(64 + b) * 1024 + t0 + tid];
    s_col[tid] = 0ULL;

    uint32_t base = smem_u32(dsm);

#define LOAD_CHUNK(c, st) do { \
    uint32_t ab = base + (st) * 49152, bb2 = ab + 16384; \
    _Pragma("unroll") \
    for (int it = 0; it < 4; it++) { \
        int idx = it * 256 + tid, row = idx >> 3, u = idx & 7; \
        cp16(ab + (uint32_t)row * 128 + (uint32_t)((u ^ (row & 7)) << 4), \
             Aq + (size_t)row * 512 + (c) * 128 + u * 16); \
    } \
    _Pragma("unroll") \
    for (int it = 0; it < 8; it++) { \
        int idx = it * 256 + tid, row = idx >> 3, u = idx & 7; \
        cp16(bb2 + (uint32_t)row * 128 + (uint32_t)((u ^ (row & 7)) << 4), \
             Bq + (size_t)row * 512 + (c) * 128 + u * 16); \
    } \
    CP_COMMIT(); } while (0)

    LOAD_CHUNK(0, 0);
    LOAD_CHUNK(1, 1);

    int wm = wid & 1, wn = wid >> 1;
    int row_in = lane & 15, ub = lane >> 4;
    uint32_t acc[4][8][2];
#pragma unroll
    for (int mi = 0; mi < 4; mi++)
#pragma unroll
        for (int ni = 0; ni < 8; ni++) { acc[mi][ni][0] = 0u; acc[mi][ni][1] = 0u; }

#define DO_CHUNK(C, W) do { \
    asm volatile("cp.async.wait_group %0;\n" :: "n"(W) : "memory"); \
    __syncthreads(); \
    uint32_t ab = base + ((C) & 1) * 49152, bb2 = ab + 16384; \
    _Pragma("unroll") \
    for (int ks = 0; ks < 4; ks++) { \
        int u = ks * 2 + ub; \
        uint32_t af[4][4], bfr[8][2]; \
        _Pragma("unroll") \
        for (int mi = 0; mi < 4; mi++) { \
            int r = wm * 64 + mi * 16 + row_in; \
            ldsm4(af[mi][0], af[mi][1], af[mi][2], af[mi][3], \
                  ab + (uint32_t)r * 128 + (uint32_t)((u ^ (r & 7)) << 4)); \
        } \
        _Pragma("unroll") \
        for (int np = 0; np < 4; np++) { \
            int r = wn * 64 + np * 16 + row_in; \
            uint32_t r0, r1, r2, r3; \
            ldsm4(r0, r1, r2, r3, \
                  bb2 + (uint32_t)r * 128 + (uint32_t)((u ^ (r & 7)) << 4)); \
            bfr[np * 2][0] = r0; bfr[np * 2][1] = r2; \
            bfr[np * 2 + 1][0] = r1; bfr[np * 2 + 1][1] = r3; \
        } \
        _Pragma("unroll") \
        for (int mi = 0; mi < 4; mi++) \
            _Pragma("unroll") \
            for (int ni = 0; ni < 8; ni++) \
                mma16816h(acc[mi][ni], af[mi], bfr[ni]); \
    } \
    if ((C) < 2) { __syncthreads(); LOAD_CHUNK((C) + 2, (C) & 1); } } while (0)

    DO_CHUNK(0, 1);
    DO_CHUNK(1, 1);
    DO_CHUNK(2, 1);
    DO_CHUNK(3, 0);
#undef DO_CHUNK
#undef LOAD_CHUNK

    int g = lane >> 2, tg = lane & 3;
#pragma unroll
    for (int mi = 0; mi < 4; mi++)
#pragma unroll
        for (int rh = 0; rh < 2; rh++) {
            unsigned long long best = 0ULL;
#pragma unroll
            for (int ni = 0; ni < 8; ni++) {
                float2 v = __half22float2(*reinterpret_cast<__half2*>(&acc[mi][ni][rh]));
                int tl0 = wn * 64 + ni * 8 + 2 * tg;
                unsigned long long k0 = packkey(v.x * kf[tl0], (uint32_t)(t0 + tl0));
                unsigned long long k1 = packkey(v.y * kf[tl0 + 1], (uint32_t)(t0 + tl0 + 1));
                if (k0 > best) best = k0;
                if (k1 > best) best = k1;
            }
            unsigned long long o;
            o = shflx64(best, 1); best = (o > best) ? o : best;
            o = shflx64(best, 2); best = (o > best) ? o : best;
            if (tg == 0)
                atomicMax(&s_row[wm * 64 + mi * 16 + g + 8 * rh], best);
        }
#pragma unroll
    for (int ni = 0; ni < 8; ni++)
#pragma unroll
        for (int cp = 0; cp < 2; cp++) {
            int tl = wn * 64 + ni * 8 + 2 * tg + cp;
            unsigned long long best = 0ULL;
#pragma unroll
            for (int mi = 0; mi < 4; mi++)
#pragma unroll
                for (int rh = 0; rh < 2; rh++) {
                    __half2 h = *reinterpret_cast<__half2*>(&acc[mi][ni][rh]);
                    float vv = cp ? __high2float(h) : __low2float(h);
                    int sl = wm * 64 + mi * 16 + g + 8 * rh;
                    unsigned long long k2 = packkey(vv * qf[sl], (uint32_t)(s0 + sl));
                    if (k2 > best) best = k2;
                }
            unsigned long long o;
            o = shflx64(best, 4);  best = (o > best) ? o : best;
            o = shflx64(best, 8);  best = (o > best) ? o : best;
            o = shflx64(best, 16); best = (o > best) ? o : best;
            if (g == 0) atomicMax(&s_col[tl], best);
        }
    __syncthreads();
    if (tid < 128) atomicMax(&d_rowbest[(size_t)b * 1024 + s0 + tid], s_row[tid]);
    atomicMax(&d_colbest[(size_t)b * 1024 + t0 + tid], s_col[tid]);
}

// ---------------- dense losses ----------------
__global__ void __launch_bounds__(256) k_dense(const float* __restrict__ adq,
                                               const float* __restrict__ adk) {
    int b = blockIdx.y, dir = blockIdx.z, s0 = blockIdx.x * 128;
    const float* xA = d_xn[dir] + (size_t)b * 1024 * 128;
    const float* xB = d_xn[dir ^ 1] + (size_t)b * 1024 * 128;
    const float* ad = dir ? adq : adk;
    const unsigned long long* best = dir ? d_colbest : d_rowbest;

    __shared__ __align__(16) float sbuf[128 * 64 + 128];
    float* Ls = sbuf;
    float* posv = sbuf + 128 * 64;
    float* xs = sbuf;
    float* ads = sbuf + 128 * 33;

    int tid = threadIdx.x, sgp = tid >> 3, jg = tid & 7;
    float accL[4][8];
#pragma unroll
    for (int i = 0; i < 4; i++)
#pragma unroll
        for (int k = 0; k < 8; k++) accL[i][k] = 0.0f;

    for (int cc = 0; cc < 4; cc++) {
        __syncthreads();
        int c0 = cc * 32;
#pragma unroll
        for (int it = 0; it < 16; it++) {
            int idx = it * 256 + tid, r = idx >> 5, c = idx & 31;
            xs[r * 33 + c] = xA[(size_t)(s0 + r) * 128 + c0 + c];
        }
#pragma unroll
        for (int it = 0; it < 8; it++) {
            int idx = it * 256 + tid, j = idx >> 5, c = idx & 31;
            ads[j * 33 + c] = ad[j * 128 + c0 + c];
        }
        __syncthreads();
#pragma unroll 4
        for (int c = 0; c < 32; c++) {
            float a[4], bb[8];
#pragma unroll
            for (int i = 0; i < 4; i++) a[i] = xs[(sgp * 4 + i) * 33 + c];
#pragma unroll
            for (int k = 0; k < 8; k++) bb[k] = ads[(jg * 8 + k) * 33 + c];
#pragma unroll
            for (int i = 0; i < 4; i++)
#pragma unroll
                for (int k = 0; k < 8; k++) accL[i][k] += a[i] * bb[k];
        }
    }
    __syncthreads();
#pragma unroll
    for (int i = 0; i < 4; i++)
#pragma unroll
        for (int k = 0; k < 8; k++)
            Ls[(sgp * 4 + i) * 64 + jg * 8 + k] = accL[i][k] * TINV;

    int lane = tid & 31, w = tid >> 5;
    for (int rr = 0; rr < 16; rr++) {
        int r = w * 16 + rr, sgl = s0 + r;
        unsigned long long bk = best[b * 1024 + sgl];
        int ind = (int)(0xFFFFFFFFu - (uint32_t)(bk & 0xFFFFFFFFull));
        float sum = 0.0f;
#pragma unroll
        for (int c = lane; c < 128; c += 32)
            sum += xA[(size_t)sgl * 128 + c] * xB[(size_t)ind * 128 + c];
#pragma unroll
        for (int off = 16; off; off >>= 1) sum += __shfl_xor_sync(0xFFFFFFFFu, sum, off);
        if (lane == 0) posv[r] = sum * TINV;
    }
    __syncthreads();

    float wsum = 0.0f;
    for (int rr = 0; rr < 16; rr++) {
        int r = w * 16 + rr;
        float v0 = Ls[r * 64 + lane], v1 = Ls[r * 64 + lane + 32];
        if (lane == b) v0 = -1e30f;
        if (lane + 32 == b) v1 = -1e30f;
        float pos = posv[r];
        float mx = fmaxf(fmaxf(v0, v1), pos);
#pragma unroll
        for (int off = 16; off; off >>= 1) mx = fmaxf(mx, __shfl_xor_sync(0xFFFFFFFFu, mx, off));
        float e = expf(v0 - mx) + expf(v1 - mx);
#pragma unroll
        for (int off = 16; off; off >>= 1) e += __shfl_xor_sync(0xFFFFFFFFu, e, off);
        if (lane == 0) wsum += logf(e + expf(pos - mx)) + mx - pos;
    }
    if (lane == 0) atomicAdd(&d_dsum, (double)wsum);
}

__global__ void k_final(const int* __restrict__ epoch, float* __restrict__ out) {
    float g = (float)(d_gsum / 128.0);
    float d = (float)(d_dsum / 131072.0);
    out[0] = (*epoch > 0) ? (0.5f * g + 0.5f * d) : g;
}

extern "C" void kernel_launch(void* const* d_in, const int* in_sizes, int n_in,
                              void* d_out, int out_size) {
    const float* ofq = (const float*)d_in[0];
    const float* agq = (const float*)d_in[1];
    const float* xq  = (const float*)d_in[2];
    const float* adq = (const float*)d_in[3];
    const float* ofk = (const float*)d_in[4];
    const float* agk = (const float*)d_in[5];
    const float* xk  = (const float*)d_in[6];
    const float* adk = (const float*)d_in[7];
    const int* epoch = (const int*)d_in[8];
    float* out = (float*)d_out;

    cudaFuncSetAttribute(k_simargmax, cudaFuncAttributeMaxDynamicSharedMemorySize, SIM_SMEM);

    k_agn<<<128, 128>>>(agq, agk);
    k_global<<<128, 128>>>();
    k_prep_of<<<dim3(32, 128), 256>>>(ofq, ofk);
    k_prep_x<<<dim3(32, 128), 256>>>(xq, xk);
    k_simargmax<<<dim3(4, 8, 64), 256, SIM_SMEM>>>();
    k_dense<<<dim3(8, 64, 2), 256>>>(adq, adk);
    k_final<<<1, 1>>>(epoch, out);
}

// round 8
// speedup vs baseline: 1.6108x; 1.2414x over previous
#include <cuda_runtime.h>
#include <cuda_fp16.h>
#include <stdint.h>

#define TINV 10.0f

__device__ float d_agn[128 * 128];
__device__ float d_ofinv[128 * 1024];
__device__ __half d_ofh[128ull * 1024 * 256];  // [bb][s][d] f16; bb: q 0-63, k 64-127
__device__ float d_xn[2][64 * 1024 * 128];     // normalized x, [b][s][c] f32
__device__ __half d_xh[2][64 * 1024 * 128];    // normalized x, f16 copy
__device__ unsigned long long d_rowbest[64 * 1024];
__device__ unsigned long long d_colbest[64 * 1024];
__device__ double d_gsum, d_dsum;

// ---------------- helpers ----------------
__device__ __forceinline__ uint32_t smem_u32(const void* p) {
    uint32_t a;
    asm("{ .reg .u64 t; cvta.to.shared.u64 t, %1; cvt.u32.u64 %0, t; }" : "=r"(a) : "l"(p));
    return a;
}
__device__ __forceinline__ uint32_t fkey(float f) {
    uint32_t u = __float_as_uint(f);
    return (u & 0x80000000u) ? ~u : (u | 0x80000000u);
}
__device__ __forceinline__ unsigned long long packkey(float v, uint32_t idx) {
    return ((unsigned long long)fkey(v) << 32) | (unsigned long long)(0xFFFFFFFFu - idx);
}
__device__ __forceinline__ unsigned long long shflx64(unsigned long long v, int m) {
    return __shfl_xor_sync(0xFFFFFFFFu, v, m);
}
__device__ __forceinline__ void cp16(uint32_t dst, const void* src) {
    asm volatile("cp.async.cg.shared.global [%0],[%1],16;\n" :: "r"(dst), "l"(src));
}
#define CP_COMMIT() asm volatile("cp.async.commit_group;\n" ::: "memory")
__device__ __forceinline__ void ldsm4(uint32_t& r0, uint32_t& r1, uint32_t& r2,
                                      uint32_t& r3, uint32_t a) {
    asm volatile("ldmatrix.sync.aligned.m8n8.x4.shared.b16 {%0,%1,%2,%3},[%4];\n"
                 : "=r"(r0), "=r"(r1), "=r"(r2), "=r"(r3) : "r"(a));
}
__device__ __forceinline__ void mma16816h(uint32_t* c, const uint32_t* a, const uint32_t* b) {
    asm volatile("mma.sync.aligned.m16n8k16.row.col.f16.f16.f16.f16 "
                 "{%0,%1},{%2,%3,%4,%5},{%6,%7},{%0,%1};\n"
                 : "+r"(c[0]), "+r"(c[1])
                 : "r"(a[0]), "r"(a[1]), "r"(a[2]), "r"(a[3]), "r"(b[0]), "r"(b[1]));
}
__device__ __forceinline__ void mma16816f(float* c, const uint32_t* a, const uint32_t* b) {
    asm volatile("mma.sync.aligned.m16n8k16.row.col.f32.f16.f16.f32 "
                 "{%0,%1,%2,%3},{%4,%5,%6,%7},{%8,%9},{%0,%1,%2,%3};\n"
                 : "+f"(c[0]), "+f"(c[1]), "+f"(c[2]), "+f"(c[3])
                 : "r"(a[0]), "r"(a[1]), "r"(a[2]), "r"(a[3]), "r"(b[0]), "r"(b[1]));
}

// ---------------- agn (+ scratch init folded in) ----------------
__global__ void k_agn(const float* __restrict__ agq, const float* __restrict__ agk) {
    int row = blockIdx.x, c = threadIdx.x;
    int gt = row * 128 + c;
#pragma unroll
    for (int i = 0; i < 4; i++) {
        d_rowbest[gt * 4 + i] = 0ULL;
        d_colbest[gt * 4 + i] = 0ULL;
    }
    if (gt == 0) { d_gsum = 0.0; d_dsum = 0.0; }

    const float* src = (row < 64) ? (agq + row * 128) : (agk + (row - 64) * 128);
    float v = src[c];
    __shared__ float red[128];
    red[c] = v * v; __syncthreads();
    for (int off = 64; off; off >>= 1) { if (c < off) red[c] += red[c + off]; __syncthreads(); }
    d_agn[row * 128 + c] = v / fmaxf(sqrtf(red[0]), 1e-12f);
}
__global__ void k_global() {
    int i = blockIdx.x, j = threadIdx.x;
    __shared__ float ai[128], red[128], s_pos;
    ai[j] = d_agn[i * 128 + j];
    __syncthreads();
    float dot = 0.0f;
#pragma unroll 8
    for (int c = 0; c < 128; c++) dot += ai[c] * d_agn[j * 128 + c];
    float lg = dot * TINV;
    if (j == ((i + 64) & 127)) s_pos = lg;
    float v = (j == i) ? -1e30f : lg;
    red[j] = v; __syncthreads();
    for (int off = 64; off; off >>= 1) { if (j < off) red[j] = fmaxf(red[j], red[j + off]); __syncthreads(); }
    float mx = red[0]; __syncthreads();
    red[j] = expf(v - mx); __syncthreads();
    for (int off = 64; off; off >>= 1) { if (j < off) red[j] += red[j + off]; __syncthreads(); }
    if (j == 0) atomicAdd(&d_gsum, (double)(logf(red[0]) + mx - s_pos));
}

// ---------------- of: transpose -> [s][d] f16 + col inv-norms ----------------
__global__ void __launch_bounds__(256) k_prep_of(const float* __restrict__ ofq,
                                                 const float* __restrict__ ofk) {
    __shared__ float sh[32 * 257];
    int bb = blockIdx.y, s0 = blockIdx.x * 32, tid = threadIdx.x;
    const float* p = (bb < 64 ? ofq : ofk) + (size_t)(bb & 63) * 256 * 1024;
#pragma unroll
    for (int it = 0; it < 8; it++) {
        int idx = it * 256 + tid;
        int dd = idx >> 3, s4 = idx & 7;
        float4 v = *(const float4*)&p[(size_t)dd * 1024 + s0 + s4 * 4];
        sh[(s4 * 4 + 0) * 257 + dd] = v.x;
        sh[(s4 * 4 + 1) * 257 + dd] = v.y;
        sh[(s4 * 4 + 2) * 257 + dd] = v.z;
        sh[(s4 * 4 + 3) * 257 + dd] = v.w;
    }
    __syncthreads();
    int s = tid >> 3, part = tid & 7, d0 = part * 32;
    const float* row = &sh[s * 257 + d0];
    float acc = 0.0f;
    uint32_t pk[16];
#pragma unroll
    for (int ii = 0; ii < 16; ii++) {
        int i = (ii + part * 2) & 15;
        float a = row[2 * i], b2 = row[2 * i + 1];
        acc += a * a + b2 * b2;
        __half2 h = __floats2half2_rn(a, b2);
        pk[i] = *reinterpret_cast<uint32_t*>(&h);
    }
    acc += __shfl_xor_sync(0xFFFFFFFFu, acc, 1);
    acc += __shfl_xor_sync(0xFFFFFFFFu, acc, 2);
    acc += __shfl_xor_sync(0xFFFFFFFFu, acc, 4);
    if (part == 0) d_ofinv[bb * 1024 + s0 + s] = 1.0f / fmaxf(sqrtf(acc), 1e-12f);
    uint4* dst = (uint4*)(d_ofh + ((size_t)bb * 1024 + s0 + s) * 256 + d0);
#pragma unroll
    for (int q = 0; q < 4; q++)
        dst[q] = make_uint4(pk[q * 4], pk[q * 4 + 1], pk[q * 4 + 2], pk[q * 4 + 3]);
}

// ---------------- x: normalize over C + transpose (f32 + f16 outputs) ----------
__global__ void __launch_bounds__(256) k_prep_x(const float* __restrict__ xq,
                                                const float* __restrict__ xk) {
    __shared__ float sh[128 * 33];
    __shared__ float invs[32];
    int bb = blockIdx.y, s0 = blockIdx.x * 32, tid = threadIdx.x;
    const float* src = (bb < 64 ? xq : xk) + (size_t)(bb & 63) * 128 * 1024;
    int side = bb < 64 ? 0 : 1;
    float* dst = d_xn[side] + (size_t)(bb & 63) * 1024 * 128;
    __half* dsth = d_xh[side] + (size_t)(bb & 63) * 1024 * 128;
#pragma unroll
    for (int it = 0; it < 4; it++) {
        int idx = it * 256 + tid;
        int c = idx >> 3, s4 = idx & 7;
        float4 v = *(const float4*)&src[(size_t)c * 1024 + s0 + s4 * 4];
        sh[c * 33 + s4 * 4 + 0] = v.x;
        sh[c * 33 + s4 * 4 + 1] = v.y;
        sh[c * 33 + s4 * 4 + 2] = v.z;
        sh[c * 33 + s4 * 4 + 3] = v.w;
    }
    __syncthreads();
    if (tid < 32) {
        float acc = 0.0f;
#pragma unroll 8
        for (int c = 0; c < 128; c++) { float v = sh[c * 33 + tid]; acc += v * v; }
        invs[tid] = 1.0f / fmaxf(sqrtf(acc), 1e-12f);
    }
    __syncthreads();
#pragma unroll
    for (int it = 0; it < 8; it++) {
        int idx = it * 256 + tid, s = idx >> 6, c2 = (idx & 63) * 2;
        float inv = invs[s];
        float a = sh[c2 * 33 + s] * inv, b2 = sh[(c2 + 1) * 33 + s] * inv;
        float2* d2 = (float2*)&dst[(size_t)(s0 + s) * 128 + c2];
        *d2 = make_float2(a, b2);
        __half2 h = __floats2half2_rn(a, b2);
        *(uint32_t*)&dsth[(size_t)(s0 + s) * 128 + c2] = *reinterpret_cast<uint32_t*>(&h);
    }
}

// ---------------- sim GEMM (f16 mma, f16 acc, 2-stage pipeline) + dual argmax ----
#define SIM_SMEM 98304
__global__ void __launch_bounds__(256, 2) k_simargmax() {
    extern __shared__ __align__(16) char dsm[];
    __shared__ float qf[128], kf[256];
    __shared__ unsigned long long s_row[128], s_col[256];
    int tid = threadIdx.x, lane = tid & 31, wid = tid >> 5;
    int b = blockIdx.z, s0 = blockIdx.y * 128, t0 = blockIdx.x * 256;
    const char* Aq = (const char*)(d_ofh + ((size_t)b * 1024 + s0) * 256);
    const char* Bq = (const char*)(d_ofh + ((size_t)(64 + b) * 1024 + t0) * 256);

    if (tid < 128) { qf[tid] = d_ofinv[b * 1024 + s0 + tid]; s_row[tid] = 0ULL; }
    kf[tid] = d_ofinv[(64 + b) * 1024 + t0 + tid];
    s_col[tid] = 0ULL;

    uint32_t base = smem_u32(dsm);

#define LOAD_CHUNK(c, st) do { \
    uint32_t ab = base + (st) * 49152, bb2 = ab + 16384; \
    _Pragma("unroll") \
    for (int it = 0; it < 4; it++) { \
        int idx = it * 256 + tid, row = idx >> 3, u = idx & 7; \
        cp16(ab + (uint32_t)row * 128 + (uint32_t)((u ^ (row & 7)) << 4), \
             Aq + (size_t)row * 512 + (c) * 128 + u * 16); \
    } \
    _Pragma("unroll") \
    for (int it = 0; it < 8; it++) { \
        int idx = it * 256 + tid, row = idx >> 3, u = idx & 7; \
        cp16(bb2 + (uint32_t)row * 128 + (uint32_t)((u ^ (row & 7)) << 4), \
             Bq + (size_t)row * 512 + (c) * 128 + u * 16); \
    } \
    CP_COMMIT(); } while (0)

    LOAD_CHUNK(0, 0);
    LOAD_CHUNK(1, 1);

    int wm = wid & 1, wn = wid >> 1;
    int row_in = lane & 15, ub = lane >> 4;
    uint32_t acc[4][8][2];
#pragma unroll
    for (int mi = 0; mi < 4; mi++)
#pragma unroll
        for (int ni = 0; ni < 8; ni++) { acc[mi][ni][0] = 0u; acc[mi][ni][1] = 0u; }

#define DO_CHUNK(C, W) do { \
    asm volatile("cp.async.wait_group %0;\n" :: "n"(W) : "memory"); \
    __syncthreads(); \
    uint32_t ab = base + ((C) & 1) * 49152, bb2 = ab + 16384; \
    _Pragma("unroll") \
    for (int ks = 0; ks < 4; ks++) { \
        int u = ks * 2 + ub; \
        uint32_t af[4][4], bfr[8][2]; \
        _Pragma("unroll") \
        for (int mi = 0; mi < 4; mi++) { \
            int r = wm * 64 + mi * 16 + row_in; \
            ldsm4(af[mi][0], af[mi][1], af[mi][2], af[mi][3], \
                  ab + (uint32_t)r * 128 + (uint32_t)((u ^ (r & 7)) << 4)); \
        } \
        _Pragma("unroll") \
        for (int np = 0; np < 4; np++) { \
            int r = wn * 64 + np * 16 + row_in; \
            uint32_t r0, r1, r2, r3; \
            ldsm4(r0, r1, r2, r3, \
                  bb2 + (uint32_t)r * 128 + (uint32_t)((u ^ (r & 7)) << 4)); \
            bfr[np * 2][0] = r0; bfr[np * 2][1] = r2; \
            bfr[np * 2 + 1][0] = r1; bfr[np * 2 + 1][1] = r3; \
        } \
        _Pragma("unroll") \
        for (int mi = 0; mi < 4; mi++) \
            _Pragma("unroll") \
            for (int ni = 0; ni < 8; ni++) \
                mma16816h(acc[mi][ni], af[mi], bfr[ni]); \
    } \
    if ((C) < 2) { __syncthreads(); LOAD_CHUNK((C) + 2, (C) & 1); } } while (0)

    DO_CHUNK(0, 1);
    DO_CHUNK(1, 1);
    DO_CHUNK(2, 1);
    DO_CHUNK(3, 0);
#undef DO_CHUNK
#undef LOAD_CHUNK

    int g = lane >> 2, tg = lane & 3;
#pragma unroll
    for (int mi = 0; mi < 4; mi++)
#pragma unroll
        for (int rh = 0; rh < 2; rh++) {
            unsigned long long best = 0ULL;
#pragma unroll
            for (int ni = 0; ni < 8; ni++) {
                float2 v = __half22float2(*reinterpret_cast<__half2*>(&acc[mi][ni][rh]));
                int tl0 = wn * 64 + ni * 8 + 2 * tg;
                unsigned long long k0 = packkey(v.x * kf[tl0], (uint32_t)(t0 + tl0));
                unsigned long long k1 = packkey(v.y * kf[tl0 + 1], (uint32_t)(t0 + tl0 + 1));
                if (k0 > best) best = k0;
                if (k1 > best) best = k1;
            }
            unsigned long long o;
            o = shflx64(best, 1); best = (o > best) ? o : best;
            o = shflx64(best, 2); best = (o > best) ? o : best;
            if (tg == 0)
                atomicMax(&s_row[wm * 64 + mi * 16 + g + 8 * rh], best);
        }
#pragma unroll
    for (int ni = 0; ni < 8; ni++)
#pragma unroll
        for (int cp = 0; cp < 2; cp++) {
            int tl = wn * 64 + ni * 8 + 2 * tg + cp;
            unsigned long long best = 0ULL;
#pragma unroll
            for (int mi = 0; mi < 4; mi++)
#pragma unroll
                for (int rh = 0; rh < 2; rh++) {
                    __half2 h = *reinterpret_cast<__half2*>(&acc[mi][ni][rh]);
                    float vv = cp ? __high2float(h) : __low2float(h);
                    int sl = wm * 64 + mi * 16 + g + 8 * rh;
                    unsigned long long k2 = packkey(vv * qf[sl], (uint32_t)(s0 + sl));
                    if (k2 > best) best = k2;
                }
            unsigned long long o;
            o = shflx64(best, 4);  best = (o > best) ? o : best;
            o = shflx64(best, 8);  best = (o > best) ? o : best;
            o = shflx64(best, 16); best = (o > best) ? o : best;
            if (g == 0) atomicMax(&s_col[tl], best);
        }
    __syncthreads();
    if (tid < 128) atomicMax(&d_rowbest[(size_t)b * 1024 + s0 + tid], s_row[tid]);
    atomicMax(&d_colbest[(size_t)b * 1024 + t0 + tid], s_col[tid]);
}

// ---------------- dense losses: tensor-core neg GEMM + CE ----------------
// Per CTA: s-tile 128 x 64 j over C=128. Phase1 GEMM (f16 mma f32 acc), phase2 CE.
#define DEN_SMEM 49152
__global__ void __launch_bounds__(256, 2) k_dense(const float* __restrict__ adq,
                                                  const float* __restrict__ adk) {
    extern __shared__ __align__(16) char dsm[];
    __shared__ float posv[128];
    int b = blockIdx.y, dir = blockIdx.z, s0 = blockIdx.x * 128;
    const __half* xhA = d_xh[dir] + (size_t)b * 1024 * 128;
    const float* xA = d_xn[dir] + (size_t)b * 1024 * 128;
    const float* xB = d_xn[dir ^ 1] + (size_t)b * 1024 * 128;
    const float* ad = dir ? adq : adk;
    const unsigned long long* best = dir ? d_colbest : d_rowbest;

    int tid = threadIdx.x, lane = tid & 31, wid = tid >> 5;
    uint32_t a_base = smem_u32(dsm), b_base = a_base + 32768;
    float* Ls = (float*)dsm;

    // phase 1a: async-load A rows (128 x 256B), swizzled
#pragma unroll
    for (int it = 0; it < 8; it++) {
        int idx = it * 256 + tid, row = idx >> 4, u = idx & 15;
        cp16(a_base + (uint32_t)row * 256 + (uint32_t)(((u & 8) | ((u & 7) ^ (row & 7))) << 4),
             (const char*)xhA + (size_t)(s0 + row) * 256 + u * 16);
    }
    CP_COMMIT();
    // phase 1b: B = ad f32 -> f16, swizzled store
#pragma unroll
    for (int it = 0; it < 4; it++) {
        int idx = it * 256 + tid, j = idx >> 4, u = idx & 15;
        float4 v0 = *(const float4*)&ad[j * 128 + u * 8];
        float4 v1 = *(const float4*)&ad[j * 128 + u * 8 + 4];
        __half2 h0 = __floats2half2_rn(v0.x, v0.y), h1 = __floats2half2_rn(v0.z, v0.w);
        __half2 h2 = __floats2half2_rn(v1.x, v1.y), h3 = __floats2half2_rn(v1.z, v1.w);
        uint4 pk = make_uint4(*(uint32_t*)&h0, *(uint32_t*)&h1, *(uint32_t*)&h2, *(uint32_t*)&h3);
        *(uint4*)(dsm + 32768 + j * 256 + (((u & 8) | ((u & 7) ^ (j & 7))) << 4)) = pk;
    }
    // pos gather meanwhile (independent of smem tiles)
    for (int rr = 0; rr < 16; rr++) {
        int r = wid * 16 + rr, sgl = s0 + r;
        unsigned long long bk = best[b * 1024 + sgl];
        int ind = (int)(0xFFFFFFFFu - (uint32_t)(bk & 0xFFFFFFFFull));
        float sum = 0.0f;
#pragma unroll
        for (int c = lane; c < 128; c += 32)
            sum += xA[(size_t)sgl * 128 + c] * xB[(size_t)ind * 128 + c];
#pragma unroll
        for (int off = 16; off; off >>= 1) sum += __shfl_xor_sync(0xFFFFFFFFu, sum, off);
        if (lane == 0) posv[r] = sum * TINV;
    }
    asm volatile("cp.async.wait_group 0;\n" ::: "memory");
    __syncthreads();

    // phase 1c: GEMM 128x64x128, warp tiles 32x32 (wm 0..3, wn 0..1)
    int wm = wid & 3, wn = wid >> 2;
    int row_in = lane & 15, ub = lane >> 4;
    float acc[2][4][4];
#pragma unroll
    for (int mi = 0; mi < 2; mi++)
#pragma unroll
        for (int ni = 0; ni < 4; ni++)
#pragma unroll
            for (int r = 0; r < 4; r++) acc[mi][ni][r] = 0.0f;
#pragma unroll
    for (int ks = 0; ks < 8; ks++) {
        int u = ks * 2 + ub;
        uint32_t af[2][4], bfr[4][2];
#pragma unroll
        for (int mi = 0; mi < 2; mi++) {
            int r = wm * 32 + mi * 16 + row_in;
            ldsm4(af[mi][0], af[mi][1], af[mi][2], af[mi][3],
                  a_base + (uint32_t)r * 256 + (uint32_t)(((u & 8) | ((u & 7) ^ (r & 7))) << 4));
        }
#pragma unroll
        for (int np = 0; np < 2; np++) {
            int r = wn * 32 + np * 16 + row_in;
            uint32_t r0, r1, r2, r3;
            ldsm4(r0, r1, r2, r3,
                  b_base + (uint32_t)r * 256 + (uint32_t)(((u & 8) | ((u & 7) ^ (r & 7))) << 4));
            bfr[np * 2][0] = r0; bfr[np * 2][1] = r2;
            bfr[np * 2 + 1][0] = r1; bfr[np * 2 + 1][1] = r3;
        }
#pragma unroll
        for (int mi = 0; mi < 2; mi++)
#pragma unroll
            for (int ni = 0; ni < 4; ni++)
                mma16816f(acc[mi][ni], af[mi], bfr[ni]);
    }
    __syncthreads();  // done reading As/Bs; reuse as Ls

    int g = lane >> 2, tg = lane & 3;
#pragma unroll
    for (int mi = 0; mi < 2; mi++)
#pragma unroll
        for (int ni = 0; ni < 4; ni++)
#pragma unroll
            for (int rh = 0; rh < 2; rh++)
#pragma unroll
                for (int cp = 0; cp < 2; cp++) {
                    int r = wm * 32 + mi * 16 + g + 8 * rh;
                    int c = wn * 32 + ni * 8 + 2 * tg + cp;
                    Ls[r * 65 + c] = acc[mi][ni][rh * 2 + cp] * TINV;
                }
    __syncthreads();

    // phase 2: CE per row
    float wsum = 0.0f;
    for (int rr = 0; rr < 16; rr++) {
        int r = wid * 16 + rr;
        float v0 = Ls[r * 65 + lane], v1 = Ls[r * 65 + lane + 32];
        if (lane == b) v0 = -1e30f;
        if (lane + 32 == b) v1 = -1e30f;
        float pos = posv[r];
        float mx = fmaxf(fmaxf(v0, v1), pos);
#pragma unroll
        for (int off = 16; off; off >>= 1) mx = fmaxf(mx, __shfl_xor_sync(0xFFFFFFFFu, mx, off));
        float e = expf(v0 - mx) + expf(v1 - mx);
#pragma unroll
        for (int off = 16; off; off >>= 1) e += __shfl_xor_sync(0xFFFFFFFFu, e, off);
        if (lane == 0) wsum += logf(e + expf(pos - mx)) + mx - pos;
    }
    if (lane == 0) atomicAdd(&d_dsum, (double)wsum);
}

__global__ void k_final(const int* __restrict__ epoch, float* __restrict__ out) {
    float g = (float)(d_gsum / 128.0);
    float d = (float)(d_dsum / 131072.0);
    out[0] = (*epoch > 0) ? (0.5f * g + 0.5f * d) : g;
}

extern "C" void kernel_launch(void* const* d_in, const int* in_sizes, int n_in,
                              void* d_out, int out_size) {
    const float* ofq = (const float*)d_in[0];
    const float* agq = (const float*)d_in[1];
    const float* xq  = (const float*)d_in[2];
    const float* adq = (const float*)d_in[3];
    const float* ofk = (const float*)d_in[4];
    const float* agk = (const float*)d_in[5];
    const float* xk  = (const float*)d_in[6];
    const float* adk = (const float*)d_in[7];
    const int* epoch = (const int*)d_in[8];
    float* out = (float*)d_out;

    cudaFuncSetAttribute(k_simargmax, cudaFuncAttributeMaxDynamicSharedMemorySize, SIM_SMEM);
    cudaFuncSetAttribute(k_dense, cudaFuncAttributeMaxDynamicSharedMemorySize, DEN_SMEM);

    k_agn<<<128, 128>>>(agq, agk);
    k_global<<<128, 128>>>();
    k_prep_of<<<dim3(32, 128), 256>>>(ofq, ofk);
    k_prep_x<<<dim3(32, 128), 256>>>(xq, xk);
    k_simargmax<<<dim3(4, 8, 64), 256, SIM_SMEM>>>();
    k_dense<<<dim3(8, 64, 2), 256, DEN_SMEM>>>(adq, adk);
    k_final<<<1, 1>>>(epoch, out);
}

// round 9
// speedup vs baseline: 1.6504x; 1.0246x over previous
#include <cuda_runtime.h>
#include <cuda_fp16.h>
#include <stdint.h>

#define TINV 10.0f

__device__ float d_agn[128 * 128];
__device__ float d_ofinv[128 * 1024];
__device__ __half d_ofh[128ull * 1024 * 256];  // [bb][s][d] f16; bb: q 0-63, k 64-127
__device__ float d_xn[2][64 * 1024 * 128];     // normalized x, [b][s][c] f32
__device__ __half d_xh[2][64 * 1024 * 128];    // normalized x, f16 copy
__device__ unsigned long long d_rowbest[64 * 1024];
__device__ unsigned long long d_colbest[64 * 1024];
__device__ double d_gsum, d_dsum;

// ---------------- helpers ----------------
__device__ __forceinline__ uint32_t smem_u32(const void* p) {
    uint32_t a;
    asm("{ .reg .u64 t; cvta.to.shared.u64 t, %1; cvt.u32.u64 %0, t; }" : "=r"(a) : "l"(p));
    return a;
}
__device__ __forceinline__ uint32_t fkey(float f) {
    uint32_t u = __float_as_uint(f);
    return (u & 0x80000000u) ? ~u : (u | 0x80000000u);
}
__device__ __forceinline__ unsigned long long packkey(float v, uint32_t idx) {
    return ((unsigned long long)fkey(v) << 32) | (unsigned long long)(0xFFFFFFFFu - idx);
}
__device__ __forceinline__ unsigned long long shflx64(unsigned long long v, int m) {
    return __shfl_xor_sync(0xFFFFFFFFu, v, m);
}
__device__ __forceinline__ void cp16(uint32_t dst, const void* src) {
    asm volatile("cp.async.cg.shared.global [%0],[%1],16;\n" :: "r"(dst), "l"(src));
}
#define CP_COMMIT() asm volatile("cp.async.commit_group;\n" ::: "memory")
__device__ __forceinline__ void ldsm4(uint32_t& r0, uint32_t& r1, uint32_t& r2,
                                      uint32_t& r3, uint32_t a) {
    asm volatile("ldmatrix.sync.aligned.m8n8.x4.shared.b16 {%0,%1,%2,%3},[%4];\n"
                 : "=r"(r0), "=r"(r1), "=r"(r2), "=r"(r3) : "r"(a));
}
__device__ __forceinline__ void mma16816h(uint32_t* c, const uint32_t* a, const uint32_t* b) {
    asm volatile("mma.sync.aligned.m16n8k16.row.col.f16.f16.f16.f16 "
                 "{%0,%1},{%2,%3,%4,%5},{%6,%7},{%0,%1};\n"
                 : "+r"(c[0]), "+r"(c[1])
                 : "r"(a[0]), "r"(a[1]), "r"(a[2]), "r"(a[3]), "r"(b[0]), "r"(b[1]));
}
__device__ __forceinline__ void mma16816f(float* c, const uint32_t* a, const uint32_t* b) {
    asm volatile("mma.sync.aligned.m16n8k16.row.col.f32.f16.f16.f32 "
                 "{%0,%1,%2,%3},{%4,%5,%6,%7},{%8,%9},{%0,%1,%2,%3};\n"
                 : "+f"(c[0]), "+f"(c[1]), "+f"(c[2]), "+f"(c[3])
                 : "r"(a[0]), "r"(a[1]), "r"(a[2]), "r"(a[3]), "r"(b[0]), "r"(b[1]));
}

// ---------------- agn (+ scratch init folded in) ----------------
__global__ void k_agn(const float* __restrict__ agq, const float* __restrict__ agk) {
    int row = blockIdx.x, c = threadIdx.x;
    int gt = row * 128 + c;
#pragma unroll
    for (int i = 0; i < 4; i++) {
        d_rowbest[gt * 4 + i] = 0ULL;
        d_colbest[gt * 4 + i] = 0ULL;
    }
    if (gt == 0) { d_gsum = 0.0; d_dsum = 0.0; }

    const float* src = (row < 64) ? (agq + row * 128) : (agk + (row - 64) * 128);
    float v = src[c];
    __shared__ float red[128];
    red[c] = v * v; __syncthreads();
    for (int off = 64; off; off >>= 1) { if (c < off) red[c] += red[c + off]; __syncthreads(); }
    d_agn[row * 128 + c] = v / fmaxf(sqrtf(red[0]), 1e-12f);
}
__global__ void k_global() {
    int i = blockIdx.x, j = threadIdx.x;
    __shared__ float ai[128], red[128], s_pos;
    ai[j] = d_agn[i * 128 + j];
    __syncthreads();
    float dot = 0.0f;
#pragma unroll 8
    for (int c = 0; c < 128; c++) dot += ai[c] * d_agn[j * 128 + c];
    float lg = dot * TINV;
    if (j == ((i + 64) & 127)) s_pos = lg;
    float v = (j == i) ? -1e30f : lg;
    red[j] = v; __syncthreads();
    for (int off = 64; off; off >>= 1) { if (j < off) red[j] = fmaxf(red[j], red[j + off]); __syncthreads(); }
    float mx = red[0]; __syncthreads();
    red[j] = expf(v - mx); __syncthreads();
    for (int off = 64; off; off >>= 1) { if (j < off) red[j] += red[j + off]; __syncthreads(); }
    if (j == 0) atomicAdd(&d_gsum, (double)(logf(red[0]) + mx - s_pos));
}

// ---------------- of: transpose -> [s][d] f16 + col inv-norms ----------------
__global__ void __launch_bounds__(256) k_prep_of(const float* __restrict__ ofq,
                                                 const float* __restrict__ ofk) {
    __shared__ float sh[32 * 257];
    int bb = blockIdx.y, s0 = blockIdx.x * 32, tid = threadIdx.x;
    const float* p = (bb < 64 ? ofq : ofk) + (size_t)(bb & 63) * 256 * 1024;
#pragma unroll
    for (int it = 0; it < 8; it++) {
        int idx = it * 256 + tid;
        int dd = idx >> 3, s4 = idx & 7;
        float4 v = *(const float4*)&p[(size_t)dd * 1024 + s0 + s4 * 4];
        sh[(s4 * 4 + 0) * 257 + dd] = v.x;
        sh[(s4 * 4 + 1) * 257 + dd] = v.y;
        sh[(s4 * 4 + 2) * 257 + dd] = v.z;
        sh[(s4 * 4 + 3) * 257 + dd] = v.w;
    }
    __syncthreads();
    int s = tid >> 3, part = tid & 7, d0 = part * 32;
    const float* row = &sh[s * 257 + d0];
    float acc = 0.0f;
    uint32_t pk[16];
#pragma unroll
    for (int ii = 0; ii < 16; ii++) {
        int i = (ii + part * 2) & 15;
        float a = row[2 * i], b2 = row[2 * i + 1];
        acc += a * a + b2 * b2;
        __half2 h = __floats2half2_rn(a, b2);
        pk[i] = *reinterpret_cast<uint32_t*>(&h);
    }
    acc += __shfl_xor_sync(0xFFFFFFFFu, acc, 1);
    acc += __shfl_xor_sync(0xFFFFFFFFu, acc, 2);
    acc += __shfl_xor_sync(0xFFFFFFFFu, acc, 4);
    if (part == 0) d_ofinv[bb * 1024 + s0 + s] = 1.0f / fmaxf(sqrtf(acc), 1e-12f);
    uint4* dst = (uint4*)(d_ofh + ((size_t)bb * 1024 + s0 + s) * 256 + d0);
#pragma unroll
    for (int q = 0; q < 4; q++)
        dst[q] = make_uint4(pk[q * 4], pk[q * 4 + 1], pk[q * 4 + 2], pk[q * 4 + 3]);
}

// ---------------- x: normalize over C + transpose (f32 + f16 outputs) ----------
__global__ void __launch_bounds__(256) k_prep_x(const float* __restrict__ xq,
                                                const float* __restrict__ xk) {
    __shared__ float sh[128 * 33];
    __shared__ float invs[32];
    int bb = blockIdx.y, s0 = blockIdx.x * 32, tid = threadIdx.x;
    const float* src = (bb < 64 ? xq : xk) + (size_t)(bb & 63) * 128 * 1024;
    int side = bb < 64 ? 0 : 1;
    float* dst = d_xn[side] + (size_t)(bb & 63) * 1024 * 128;
    __half* dsth = d_xh[side] + (size_t)(bb & 63) * 1024 * 128;
#pragma unroll
    for (int it = 0; it < 4; it++) {
        int idx = it * 256 + tid;
        int c = idx >> 3, s4 = idx & 7;
        float4 v = *(const float4*)&src[(size_t)c * 1024 + s0 + s4 * 4];
        sh[c * 33 + s4 * 4 + 0] = v.x;
        sh[c * 33 + s4 * 4 + 1] = v.y;
        sh[c * 33 + s4 * 4 + 2] = v.z;
        sh[c * 33 + s4 * 4 + 3] = v.w;
    }
    __syncthreads();
    if (tid < 32) {
        float acc = 0.0f;
#pragma unroll 8
        for (int c = 0; c < 128; c++) { float v = sh[c * 33 + tid]; acc += v * v; }
        invs[tid] = 1.0f / fmaxf(sqrtf(acc), 1e-12f);
    }
    __syncthreads();
#pragma unroll
    for (int it = 0; it < 8; it++) {
        int idx = it * 256 + tid, s = idx >> 6, c2 = (idx & 63) * 2;
        float inv = invs[s];
        float a = sh[c2 * 33 + s] * inv, b2 = sh[(c2 + 1) * 33 + s] * inv;
        float2* d2 = (float2*)&dst[(size_t)(s0 + s) * 128 + c2];
        *d2 = make_float2(a, b2);
        __half2 h = __floats2half2_rn(a, b2);
        *(uint32_t*)&dsth[(size_t)(s0 + s) * 128 + c2] = *reinterpret_cast<uint32_t*>(&h);
    }
}

// ---------------- sim GEMM (f16 mma, f16 acc, 2-stage pipeline) + dual argmax ----
#define SIM_SMEM 98304
__global__ void __launch_bounds__(256, 2) k_simargmax() {
    extern __shared__ __align__(16) char dsm[];
    __shared__ float qf[128], kf[256];
    __shared__ unsigned long long s_row[128], s_col[256];
    int tid = threadIdx.x, lane = tid & 31, wid = tid >> 5;
    int b = blockIdx.z, s0 = blockIdx.y * 128, t0 = blockIdx.x * 256;
    const char* Aq = (const char*)(d_ofh + ((size_t)b * 1024 + s0) * 256);
    const char* Bq = (const char*)(d_ofh + ((size_t)(64 + b) * 1024 + t0) * 256);

    if (tid < 128) { qf[tid] = d_ofinv[b * 1024 + s0 + tid]; s_row[tid] = 0ULL; }
    kf[tid] = d_ofinv[(64 + b) * 1024 + t0 + tid];
    s_col[tid] = 0ULL;

    uint32_t base = smem_u32(dsm);

#define LOAD_CHUNK(c, st) do { \
    uint32_t ab = base + (st) * 49152, bb2 = ab + 16384; \
    _Pragma("unroll") \
    for (int it = 0; it < 4; it++) { \
        int idx = it * 256 + tid, row = idx >> 3, u = idx & 7; \
        cp16(ab + (uint32_t)row * 128 + (uint32_t)((u ^ (row & 7)) << 4), \
             Aq + (size_t)row * 512 + (c) * 128 + u * 16); \
    } \
    _Pragma("unroll") \
    for (int it = 0; it < 8; it++) { \
        int idx = it * 256 + tid, row = idx >> 3, u = idx & 7; \
        cp16(bb2 + (uint32_t)row * 128 + (uint32_t)((u ^ (row & 7)) << 4), \
             Bq + (size_t)row * 512 + (c) * 128 + u * 16); \
    } \
    CP_COMMIT(); } while (0)

    LOAD_CHUNK(0, 0);
    LOAD_CHUNK(1, 1);

    int wm = wid & 1, wn = wid >> 1;
    int row_in = lane & 15, ub = lane >> 4;
    uint32_t acc[4][8][2];
#pragma unroll
    for (int mi = 0; mi < 4; mi++)
#pragma unroll
        for (int ni = 0; ni < 8; ni++) { acc[mi][ni][0] = 0u; acc[mi][ni][1] = 0u; }

#define DO_CHUNK(C, W) do { \
    asm volatile("cp.async.wait_group %0;\n" :: "n"(W) : "memory"); \
    __syncthreads(); \
    uint32_t ab = base + ((C) & 1) * 49152, bb2 = ab + 16384; \
    _Pragma("unroll") \
    for (int ks = 0; ks < 4; ks++) { \
        int u = ks * 2 + ub; \
        uint32_t af[4][4], bfr[8][2]; \
        _Pragma("unroll") \
        for (int mi = 0; mi < 4; mi++) { \
            int r = wm * 64 + mi * 16 + row_in; \
            ldsm4(af[mi][0], af[mi][1], af[mi][2], af[mi][3], \
                  ab + (uint32_t)r * 128 + (uint32_t)((u ^ (r & 7)) << 4)); \
        } \
        _Pragma("unroll") \
        for (int np = 0; np < 4; np++) { \
            int r = wn * 64 + np * 16 + row_in; \
            uint32_t r0, r1, r2, r3; \
            ldsm4(r0, r1, r2, r3, \
                  bb2 + (uint32_t)r * 128 + (uint32_t)((u ^ (r & 7)) << 4)); \
            bfr[np * 2][0] = r0; bfr[np * 2][1] = r2; \
            bfr[np * 2 + 1][0] = r1; bfr[np * 2 + 1][1] = r3; \
        } \
        _Pragma("unroll") \
        for (int mi = 0; mi < 4; mi++) \
            _Pragma("unroll") \
            for (int ni = 0; ni < 8; ni++) \
                mma16816h(acc[mi][ni], af[mi], bfr[ni]); \
    } \
    if ((C) < 2) { __syncthreads(); LOAD_CHUNK((C) + 2, (C) & 1); } } while (0)

    DO_CHUNK(0, 1);
    DO_CHUNK(1, 1);
    DO_CHUNK(2, 1);
    DO_CHUNK(3, 0);
#undef DO_CHUNK
#undef LOAD_CHUNK

    int g = lane >> 2, tg = lane & 3;
#pragma unroll
    for (int mi = 0; mi < 4; mi++)
#pragma unroll
        for (int rh = 0; rh < 2; rh++) {
            unsigned long long best = 0ULL;
#pragma unroll
            for (int ni = 0; ni < 8; ni++) {
                float2 v = __half22float2(*reinterpret_cast<__half2*>(&acc[mi][ni][rh]));
                int tl0 = wn * 64 + ni * 8 + 2 * tg;
                unsigned long long k0 = packkey(v.x * kf[tl0], (uint32_t)(t0 + tl0));
                unsigned long long k1 = packkey(v.y * kf[tl0 + 1], (uint32_t)(t0 + tl0 + 1));
                if (k0 > best) best = k0;
                if (k1 > best) best = k1;
            }
            unsigned long long o;
            o = shflx64(best, 1); best = (o > best) ? o : best;
            o = shflx64(best, 2); best = (o > best) ? o : best;
            if (tg == 0)
                atomicMax(&s_row[wm * 64 + mi * 16 + g + 8 * rh], best);
        }
#pragma unroll
    for (int ni = 0; ni < 8; ni++)
#pragma unroll
        for (int cp = 0; cp < 2; cp++) {
            int tl = wn * 64 + ni * 8 + 2 * tg + cp;
            unsigned long long best = 0ULL;
#pragma unroll
            for (int mi = 0; mi < 4; mi++)
#pragma unroll
                for (int rh = 0; rh < 2; rh++) {
                    __half2 h = *reinterpret_cast<__half2*>(&acc[mi][ni][rh]);
                    float vv = cp ? __high2float(h) : __low2float(h);
                    int sl = wm * 64 + mi * 16 + g + 8 * rh;
                    unsigned long long k2 = packkey(vv * qf[sl], (uint32_t)(s0 + sl));
                    if (k2 > best) best = k2;
                }
            unsigned long long o;
            o = shflx64(best, 4);  best = (o > best) ? o : best;
            o = shflx64(best, 8);  best = (o > best) ? o : best;
            o = shflx64(best, 16); best = (o > best) ? o : best;
            if (g == 0) atomicMax(&s_col[tl], best);
        }
    __syncthreads();
    if (tid < 128) atomicMax(&d_rowbest[(size_t)b * 1024 + s0 + tid], s_row[tid]);
    atomicMax(&d_colbest[(size_t)b * 1024 + t0 + tid], s_col[tid]);
}

// ---------------- dense losses: tensor-core neg GEMM + CE ----------------
#define DEN_SMEM 49152
__global__ void __launch_bounds__(256, 2) k_dense(const float* __restrict__ adq,
                                                  const float* __restrict__ adk) {
    extern __shared__ __align__(16) char dsm[];
    __shared__ float posv[128];
    int b = blockIdx.y, dir = blockIdx.z, s0 = blockIdx.x * 128;
    const __half* xhA = d_xh[dir] + (size_t)b * 1024 * 128;
    const float* xA = d_xn[dir] + (size_t)b * 1024 * 128;
    const float* xB = d_xn[dir ^ 1] + (size_t)b * 1024 * 128;
    const float* ad = dir ? adq : adk;
    const unsigned long long* best = dir ? d_colbest : d_rowbest;

    int tid = threadIdx.x, lane = tid & 31, wid = tid >> 5;
    uint32_t a_base = smem_u32(dsm), b_base = a_base + 32768;
    float* Ls = (float*)dsm;

#pragma unroll
    for (int it = 0; it < 8; it++) {
        int idx = it * 256 + tid, row = idx >> 4, u = idx & 15;
        cp16(a_base + (uint32_t)row * 256 + (uint32_t)(((u & 8) | ((u & 7) ^ (row & 7))) << 4),
             (const char*)xhA + (size_t)(s0 + row) * 256 + u * 16);
    }
    CP_COMMIT();
#pragma unroll
    for (int it = 0; it < 4; it++) {
        int idx = it * 256 + tid, j = idx >> 4, u = idx & 15;
        float4 v0 = *(const float4*)&ad[j * 128 + u * 8];
        float4 v1 = *(const float4*)&ad[j * 128 + u * 8 + 4];
        __half2 h0 = __floats2half2_rn(v0.x, v0.y), h1 = __floats2half2_rn(v0.z, v0.w);
        __half2 h2 = __floats2half2_rn(v1.x, v1.y), h3 = __floats2half2_rn(v1.z, v1.w);
        uint4 pk = make_uint4(*(uint32_t*)&h0, *(uint32_t*)&h1, *(uint32_t*)&h2, *(uint32_t*)&h3);
        *(uint4*)(dsm + 32768 + j * 256 + (((u & 8) | ((u & 7) ^ (j & 7))) << 4)) = pk;
    }
    for (int rr = 0; rr < 16; rr++) {
        int r = wid * 16 + rr, sgl = s0 + r;
        unsigned long long bk = best[b * 1024 + sgl];
        int ind = (int)(0xFFFFFFFFu - (uint32_t)(bk & 0xFFFFFFFFull));
        float sum = 0.0f;
#pragma unroll
        for (int c = lane; c < 128; c += 32)
            sum += xA[(size_t)sgl * 128 + c] * xB[(size_t)ind * 128 + c];
#pragma unroll
        for (int off = 16; off; off >>= 1) sum += __shfl_xor_sync(0xFFFFFFFFu, sum, off);
        if (lane == 0) posv[r] = sum * TINV;
    }
    asm volatile("cp.async.wait_group 0;\n" ::: "memory");
    __syncthreads();

    int wm = wid & 3, wn = wid >> 2;
    int row_in = lane & 15, ub = lane >> 4;
    float acc[2][4][4];
#pragma unroll
    for (int mi = 0; mi < 2; mi++)
#pragma unroll
        for (int ni = 0; ni < 4; ni++)
#pragma unroll
            for (int r = 0; r < 4; r++) acc[mi][ni][r] = 0.0f;
#pragma unroll
    for (int ks = 0; ks < 8; ks++) {
        int u = ks * 2 + ub;
        uint32_t af[2][4], bfr[4][2];
#pragma unroll
        for (int mi = 0; mi < 2; mi++) {
            int r = wm * 32 + mi * 16 + row_in;
            ldsm4(af[mi][0], af[mi][1], af[mi][2], af[mi][3],
                  a_base + (uint32_t)r * 256 + (uint32_t)(((u & 8) | ((u & 7) ^ (r & 7))) << 4));
        }
#pragma unroll
        for (int np = 0; np < 2; np++) {
            int r = wn * 32 + np * 16 + row_in;
            uint32_t r0, r1, r2, r3;
            ldsm4(r0, r1, r2, r3,
                  b_base + (uint32_t)r * 256 + (uint32_t)(((u & 8) | ((u & 7) ^ (r & 7))) << 4));
            bfr[np * 2][0] = r0; bfr[np * 2][1] = r2;
            bfr[np * 2 + 1][0] = r1; bfr[np * 2 + 1][1] = r3;
        }
#pragma unroll
        for (int mi = 0; mi < 2; mi++)
#pragma unroll
            for (int ni = 0; ni < 4; ni++)
                mma16816f(acc[mi][ni], af[mi], bfr[ni]);
    }
    __syncthreads();

    int g = lane >> 2, tg = lane & 3;
#pragma unroll
    for (int mi = 0; mi < 2; mi++)
#pragma unroll
        for (int ni = 0; ni < 4; ni++)
#pragma unroll
            for (int rh = 0; rh < 2; rh++)
#pragma unroll
                for (int cp = 0; cp < 2; cp++) {
                    int r = wm * 32 + mi * 16 + g + 8 * rh;
                    int c = wn * 32 + ni * 8 + 2 * tg + cp;
                    Ls[r * 65 + c] = acc[mi][ni][rh * 2 + cp] * TINV;
                }
    __syncthreads();

    float wsum = 0.0f;
    for (int rr = 0; rr < 16; rr++) {
        int r = wid * 16 + rr;
        float v0 = Ls[r * 65 + lane], v1 = Ls[r * 65 + lane + 32];
        if (lane == b) v0 = -1e30f;
        if (lane + 32 == b) v1 = -1e30f;
        float pos = posv[r];
        float mx = fmaxf(fmaxf(v0, v1), pos);
#pragma unroll
        for (int off = 16; off; off >>= 1) mx = fmaxf(mx, __shfl_xor_sync(0xFFFFFFFFu, mx, off));
        float e = expf(v0 - mx) + expf(v1 - mx);
#pragma unroll
        for (int off = 16; off; off >>= 1) e += __shfl_xor_sync(0xFFFFFFFFu, e, off);
        if (lane == 0) wsum += logf(e + expf(pos - mx)) + mx - pos;
    }
    if (lane == 0) atomicAdd(&d_dsum, (double)wsum);
}

__global__ void k_final(const int* __restrict__ epoch, float* __restrict__ out) {
    float g = (float)(d_gsum / 128.0);
    float d = (float)(d_dsum / 131072.0);
    out[0] = (*epoch > 0) ? (0.5f * g + 0.5f * d) : g;
}

extern "C" void kernel_launch(void* const* d_in, const int* in_sizes, int n_in,
                              void* d_out, int out_size) {
    const float* ofq = (const float*)d_in[0];
    const float* agq = (const float*)d_in[1];
    const float* xq  = (const float*)d_in[2];
    const float* adq = (const float*)d_in[3];
    const float* ofk = (const float*)d_in[4];
    const float* agk = (const float*)d_in[5];
    const float* xk  = (const float*)d_in[6];
    const float* adk = (const float*)d_in[7];
    const int* epoch = (const int*)d_in[8];
    float* out = (float*)d_out;

    static bool init_done = false;
    static cudaStream_t s1, s2;
    static cudaEvent_t eFork, eAgn, eGlob, ePx;
    if (!init_done) {
        cudaFuncSetAttribute(k_simargmax, cudaFuncAttributeMaxDynamicSharedMemorySize, SIM_SMEM);
        cudaFuncSetAttribute(k_dense, cudaFuncAttributeMaxDynamicSharedMemorySize, DEN_SMEM);
        cudaStreamCreateWithFlags(&s1, cudaStreamNonBlocking);
        cudaStreamCreateWithFlags(&s2, cudaStreamNonBlocking);
        cudaEventCreateWithFlags(&eFork, cudaEventDisableTiming);
        cudaEventCreateWithFlags(&eAgn, cudaEventDisableTiming);
        cudaEventCreateWithFlags(&eGlob, cudaEventDisableTiming);
        cudaEventCreateWithFlags(&ePx, cudaEventDisableTiming);
        init_done = true;
    }

    // fork side streams off the capture stream
    cudaEventRecord(eFork, 0);
    cudaStreamWaitEvent(s1, eFork, 0);
    cudaStreamWaitEvent(s2, eFork, 0);

    // s1: agn (also zeroes scratch) -> global
    k_agn<<<128, 128, 0, s1>>>(agq, agk);
    cudaEventRecord(eAgn, s1);
    k_global<<<128, 128, 0, s1>>>();
    cudaEventRecord(eGlob, s1);

    // s2: prep_x (only needed by dense)
    k_prep_x<<<dim3(32, 128), 256, 0, s2>>>(xq, xk);
    cudaEventRecord(ePx, s2);

    // main stream: prep_of -> (after agn zeroing) sim -> (after prep_x) dense -> final
    k_prep_of<<<dim3(32, 128), 256>>>(ofq, ofk);
    cudaStreamWaitEvent(0, eAgn, 0);
    k_simargmax<<<dim3(4, 8, 64), 256, SIM_SMEM>>>();
    cudaStreamWaitEvent(0, ePx, 0);
    k_dense<<<dim3(8, 64, 2), 256, DEN_SMEM>>>(adq, adk);
    cudaStreamWaitEvent(0, eGlob, 0);
    k_final<<<1, 1>>>(epoch, out);
}